// round 8
// baseline (speedup 1.0000x reference)
#include <cuda_runtime.h>
#include <cuda_bf16.h>
#include <stdint.h>

#define NN 100000
#define HH 128
#define NE 1600000
#define NL 3
#define NB 98   // scan blocks = ceil(NN/1024)

#define STRD 20              // B-chunk smem row stride in words (ldmatrix conflict-free)
#define PLANE (128 * STRD)   // one 128-row chunk plane, in words (jk kernel)
#define ASTRD 68             // A half-K plane row stride in words (128 cols bf16 = 64 words + 4 pad)

// ---------------- scratch (device globals) ----------------------------------
__device__ int   g_cnt[NN];
__device__ int   g_rowptr[NN + 1];
__device__ int   g_cursor[NN];
__device__ int   g_csr[NE];
__device__ int   g_state[NB];
__device__ int   g_aggv[NB];
__device__ int   g_prefv[NB];
__device__ float g_invdeg[NN];
__device__ float g_xs[NL][(size_t)NN * HH];
// weights pre-split to bf16 hi/lo, layout [h][k] (k contiguous)
__device__ __nv_bfloat16 g_Wb[NL][2][128 * 256];
__device__ __nv_bfloat16 g_jkWb[2][128 * 512];

// ---------------- helpers ----------------------------------------------------
__device__ __forceinline__ void cvt_hilo(float x, float y, unsigned& hi, unsigned& lo) {
    __nv_bfloat162 h = __floats2bfloat162_rn(x, y);
    float hx = __bfloat162float(h.x), hy = __bfloat162float(h.y);
    __nv_bfloat162 l = __floats2bfloat162_rn(x - hx, y - hy);
    hi = *reinterpret_cast<unsigned*>(&h);
    lo = *reinterpret_cast<unsigned*>(&l);
}

#define MMA16816(d, a, b) asm volatile( \
    "mma.sync.aligned.m16n8k16.row.col.f32.bf16.bf16.f32 " \
    "{%0,%1,%2,%3}, {%4,%5,%6,%7}, {%8,%9}, {%0,%1,%2,%3};" \
    : "+f"((d)[0]), "+f"((d)[1]), "+f"((d)[2]), "+f"((d)[3]) \
    : "r"((a)[0]), "r"((a)[1]), "r"((a)[2]), "r"((a)[3]), \
      "r"((b)[0]), "r"((b)[1]))

__device__ __forceinline__ void ldsm4(unsigned* r, uint32_t addr) {
    asm volatile("ldmatrix.sync.aligned.m8n8.x4.shared.b16 {%0,%1,%2,%3}, [%4];"
                 : "=r"(r[0]), "=r"(r[1]), "=r"(r[2]), "=r"(r[3]) : "r"(addr));
}

#define CP16(dst, src) asm volatile("cp.async.cg.shared.global [%0], [%1], 16;" :: "r"(dst), "l"(src))
#define CP_COMMIT()    asm volatile("cp.async.commit_group;")
#define CP_WAIT(n)     asm volatile("cp.async.wait_group %0;" :: "n"(n))

// ---------------- setup: zero counters/state + weight split -----------------
__global__ void init_k(const float* __restrict__ Wl, const float* __restrict__ Wr,
                       const float* __restrict__ jkW) {
    int i = blockIdx.x * blockDim.x + threadIdx.x;
    if (i < NN) { g_cnt[i] = 0; g_cursor[i] = 0; }
    if (i < NB) g_state[i] = 0;
    const int totW = NL * 128 * 256;
    float w; int dstl = -1, dsti = 0;
    if (i < totW) {
        int l = i >> 15;
        int rem = i & 32767;
        int h = rem >> 8, k = rem & 255;
        w = (k < 128) ? Wl[l * 16384 + h * 128 + k]
                      : Wr[l * 16384 + h * 128 + (k - 128)];
        dstl = l; dsti = rem;
    } else {
        int j = i - totW;
        if (j >= 128 * 512) return;
        w = jkW[j];
        dsti = j;
    }
    __nv_bfloat16 hi = __float2bfloat16(w);
    __nv_bfloat16 lo = __float2bfloat16(w - __bfloat162float(hi));
    if (dstl >= 0) { g_Wb[dstl][0][dsti] = hi; g_Wb[dstl][1][dsti] = lo; }
    else           { g_jkWb[0][dsti] = hi;     g_jkWb[1][dsti] = lo; }
}

__global__ void count_k(const int* __restrict__ dst) {
    int i = blockIdx.x * blockDim.x + threadIdx.x;
    if (i < NE) atomicAdd(&g_cnt[dst[i]], 1);
}

// single-kernel decoupled-lookback exclusive scan (98 co-resident blocks)
__global__ void scan_k() {
    __shared__ int sh[1024];
    __shared__ int s_excl;
    int bid = blockIdx.x;
    int i = bid * 1024 + (int)threadIdx.x;
    int v = (i < NN) ? g_cnt[i] : 0;
    sh[threadIdx.x] = v;
    __syncthreads();
    #pragma unroll
    for (int off = 1; off < 1024; off <<= 1) {
        int t = (threadIdx.x >= (unsigned)off) ? sh[threadIdx.x - off] : 0;
        __syncthreads();
        sh[threadIdx.x] += t;
        __syncthreads();
    }
    int total = sh[1023];
    if (threadIdx.x == 0) {
        if (bid == 0) {
            g_prefv[0] = total;
            __threadfence();
            atomicExch(&g_state[0], 2);
            s_excl = 0;
        } else {
            g_aggv[bid] = total;
            __threadfence();
            atomicExch(&g_state[bid], 1);
            int excl = 0, j = bid - 1;
            while (j >= 0) {
                int st;
                do { st = atomicAdd(&g_state[j], 0); } while (st == 0);
                if (st == 2) { excl += atomicAdd(&g_prefv[j], 0); break; }
                excl += atomicAdd(&g_aggv[j], 0);
                j--;
            }
            g_prefv[bid] = excl + total;
            __threadfence();
            atomicExch(&g_state[bid], 2);
            s_excl = excl;
        }
    }
    __syncthreads();
    int excl = s_excl;
    if (i < NN) {
        g_rowptr[i] = sh[threadIdx.x] - v + excl;
        g_invdeg[i] = 1.0f / fmaxf((float)v, 1.0f);
    }
    if (bid == NB - 1 && threadIdx.x == 1023) g_rowptr[NN] = excl + total;
}

__global__ void fill_k(const int* __restrict__ src, const int* __restrict__ dst) {
    int i = blockIdx.x * blockDim.x + threadIdx.x;
    if (i < NE) {
        int d = dst[i];
        int pos = g_rowptr[d] + atomicAdd(&g_cursor[d], 1);
        g_csr[pos] = src[i];
    }
}

// ---------------- GEMM fragments -------------------------------------------
struct Frag { unsigned aH0[4], aL0[4], aH1[4], aL1[4], bh[8][2], bl[8][2]; };

// MMA over one 32-k chunk; A from half-K planes (stride ASTRD), B from chunk buffer.
__device__ __forceinline__ void mma_chunkA(
    float acc[2][8][4], uint32_t aBase, uint32_t bBase, int wm, int wn, int lane) {
    int lr = lane & 7, lg8 = ((lane >> 3) & 1) * 8, lk4 = ((lane >> 4) & 1) * 4;
    uint32_t rowA = (uint32_t)(wm * 32 + lg8 + lr) * (ASTRD * 4);
    uint32_t rowB0 = (uint32_t)(wn * 64 + lg8 + lr) * (STRD * 4);
    const uint32_t aLoOff = 128 * ASTRD * 4;
    #pragma unroll
    for (int s = 0; s < 2; s++) {
        uint32_t kb = (uint32_t)(s * 8 + lk4) * 4;
        Frag f;
        ldsm4(f.aH0, aBase + rowA + kb);
        ldsm4(f.aH1, aBase + rowA + 16 * (ASTRD * 4) + kb);
        ldsm4(f.aL0, aBase + aLoOff + rowA + kb);
        ldsm4(f.aL1, aBase + aLoOff + rowA + 16 * (ASTRD * 4) + kb);
        #pragma unroll
        for (int nt2 = 0; nt2 < 4; nt2++) {
            unsigned t[4];
            uint32_t rb = rowB0 + (uint32_t)(nt2 * 16) * (STRD * 4) + kb;
            ldsm4(t, bBase + rb);
            f.bh[2*nt2][0] = t[0]; f.bh[2*nt2+1][0] = t[1];
            f.bh[2*nt2][1] = t[2]; f.bh[2*nt2+1][1] = t[3];
            ldsm4(t, bBase + PLANE * 4 + rb);
            f.bl[2*nt2][0] = t[0]; f.bl[2*nt2+1][0] = t[1];
            f.bl[2*nt2][1] = t[2]; f.bl[2*nt2+1][1] = t[3];
        }
        #pragma unroll
        for (int mt = 0; mt < 2; mt++) {
            const unsigned* aH = mt ? f.aH1 : f.aH0;
            const unsigned* aL = mt ? f.aL1 : f.aL0;
            #pragma unroll
            for (int nt = 0; nt < 8; nt++) {
                MMA16816(acc[mt][nt], aH, f.bh[nt]);
                MMA16816(acc[mt][nt], aH, f.bl[nt]);
                MMA16816(acc[mt][nt], aL, f.bh[nt]);
            }
        }
    }
}

// MMA for jk kernel (A in chunk layout, stride STRD)
__device__ __forceinline__ void mma_chunk(
    float acc[2][8][4], uint32_t sh_base, int cur, int wm, int wn, int lane) {
    int lr = lane & 7, lg8 = ((lane >> 3) & 1) * 8, lk4 = ((lane >> 4) & 1) * 4;
    uint32_t base = sh_base + (uint32_t)cur * 4 * PLANE * 4;
    uint32_t rowA = (uint32_t)(wm * 32 + lg8 + lr) * (STRD * 4);
    uint32_t rowB0 = (uint32_t)(wn * 64 + lg8 + lr) * (STRD * 4);
    #pragma unroll
    for (int s = 0; s < 2; s++) {
        uint32_t kb = (uint32_t)(s * 8 + lk4) * 4;
        Frag f;
        ldsm4(f.aH0, base + rowA + kb);
        ldsm4(f.aH1, base + rowA + 16 * (STRD * 4) + kb);
        ldsm4(f.aL0, base + PLANE * 4 + rowA + kb);
        ldsm4(f.aL1, base + PLANE * 4 + rowA + 16 * (STRD * 4) + kb);
        #pragma unroll
        for (int nt2 = 0; nt2 < 4; nt2++) {
            unsigned t[4];
            uint32_t rb = rowB0 + (uint32_t)(nt2 * 16) * (STRD * 4) + kb;
            ldsm4(t, base + 2 * PLANE * 4 + rb);
            f.bh[2*nt2][0] = t[0]; f.bh[2*nt2+1][0] = t[1];
            f.bh[2*nt2][1] = t[2]; f.bh[2*nt2+1][1] = t[3];
            ldsm4(t, base + 3 * PLANE * 4 + rb);
            f.bl[2*nt2][0] = t[0]; f.bl[2*nt2+1][0] = t[1];
            f.bl[2*nt2][1] = t[2]; f.bl[2*nt2+1][1] = t[3];
        }
        #pragma unroll
        for (int mt = 0; mt < 2; mt++) {
            const unsigned* aH = mt ? f.aH1 : f.aH0;
            const unsigned* aL = mt ? f.aL1 : f.aL0;
            #pragma unroll
            for (int nt = 0; nt < 8; nt++) {
                MMA16816(acc[mt][nt], aH, f.bh[nt]);
                MMA16816(acc[mt][nt], aH, f.bl[nt]);
                MMA16816(acc[mt][nt], aL, f.bh[nt]);
            }
        }
    }
}

__device__ __forceinline__ void storeA(unsigned* smem_u, int cur, int arow, int half,
                                       const float4 va[4]) {
    unsigned* Ah = smem_u + (size_t)cur * 4 * PLANE;
    unsigned* Al = Ah + PLANE;
    #pragma unroll
    for (int t = 0; t < 4; t++) {
        unsigned h0, l0, h1, l1;
        cvt_hilo(va[t].x, va[t].y, h0, l0);
        cvt_hilo(va[t].z, va[t].w, h1, l1);
        int j = arow * STRD + half * 8 + t * 2;
        Ah[j] = h0; Ah[j + 1] = h1;
        Al[j] = l0; Al[j + 1] = l1;
    }
}

// cp.async B chunk (hi+lo) into chunk buffer at byte base bDst
__device__ __forceinline__ void loadB_chunk(uint32_t bDst, int tid,
                                            const unsigned* WH, const unsigned* WL,
                                            int k0, int rowstride) {
    #pragma unroll
    for (int it = 0; it < 2; it++) {
        int c = tid + it * 256;
        int row = c >> 2, part = c & 3;
        uint32_t doff = (uint32_t)(row * STRD + part * 4) * 4;
        const unsigned* sh = WH + (size_t)row * rowstride + (k0 >> 1) + part * 4;
        const unsigned* sl = WL + (size_t)row * rowstride + (k0 >> 1) + part * 4;
        CP16(bDst + doff, sh);
        CP16(bDst + PLANE * 4 + doff, sl);
    }
}

// ---------------- fused layer: gather-agg + GEMM(K=256) + bias+LN+ReLU+res --
// smem words: Ah[128*ASTRD] Al[128*ASTRD] B[2 bufs][2 planes][PLANE] red[512]
__global__ __launch_bounds__(256, 2) void sage_layer_k(
    const float* __restrict__ emb, int layer,
    const float* __restrict__ bl_all,
    const float* __restrict__ gamma_all, const float* __restrict__ beta_all) {
    extern __shared__ unsigned smem_u[];
    unsigned* Ahp = smem_u;
    unsigned* Alp = smem_u + 128 * ASTRD;
    const uint32_t BOFF = 2u * 128 * ASTRD * 4;            // bytes
    float* red = (float*)(smem_u + 2 * 128 * ASTRD + 4 * PLANE);

    const float* __restrict__ xin = (layer == 0) ? emb : g_xs[layer - 1];
    float* __restrict__ xout = g_xs[layer];
    const unsigned* WH = (const unsigned*)g_Wb[layer][0];
    const unsigned* WL = (const unsigned*)g_Wb[layer][1];
    const float* __restrict__ bias  = bl_all + layer * 128;
    const float* __restrict__ gamma = gamma_all + layer * 128;
    const float* __restrict__ beta  = beta_all + layer * 128;

    int tid = threadIdx.x, wid = tid >> 5, lane = tid & 31;
    int wm = wid & 3, wn = wid >> 2;
    int n0 = blockIdx.x * 128;
    uint32_t sh_base = (uint32_t)__cvta_generic_to_shared(smem_u);

    // prefetch B chunk 0
    loadB_chunk(sh_base + BOFF, tid, WH, WL, 0, 128);
    CP_COMMIT();

    // ---- gather aggregation into A planes (K first half) ----
    #pragma unroll 1
    for (int it = 0; it < 16; it++) {
        int row = wid * 16 + it;
        int node = n0 + row;
        float4 acc = make_float4(0.f, 0.f, 0.f, 0.f);
        if (node < NN) {
            int beg = g_rowptr[node], end = g_rowptr[node + 1];
            const float* xb = xin + lane * 4;
            int j = beg;
            for (; j + 3 < end; j += 4) {
                int s0 = g_csr[j], s1 = g_csr[j + 1], s2 = g_csr[j + 2], s3 = g_csr[j + 3];
                float4 v0 = *(const float4*)(xb + (size_t)s0 * HH);
                float4 v1 = *(const float4*)(xb + (size_t)s1 * HH);
                float4 v2 = *(const float4*)(xb + (size_t)s2 * HH);
                float4 v3 = *(const float4*)(xb + (size_t)s3 * HH);
                acc.x += (v0.x + v1.x) + (v2.x + v3.x);
                acc.y += (v0.y + v1.y) + (v2.y + v3.y);
                acc.z += (v0.z + v1.z) + (v2.z + v3.z);
                acc.w += (v0.w + v1.w) + (v2.w + v3.w);
            }
            for (; j < end; j++) {
                int s0 = g_csr[j];
                float4 v0 = *(const float4*)(xb + (size_t)s0 * HH);
                acc.x += v0.x; acc.y += v0.y; acc.z += v0.z; acc.w += v0.w;
            }
            float inv = g_invdeg[node];
            acc.x *= inv; acc.y *= inv; acc.z *= inv; acc.w *= inv;
        }
        unsigned h0, l0, h1, l1;
        cvt_hilo(acc.x, acc.y, h0, l0);
        cvt_hilo(acc.z, acc.w, h1, l1);
        int jj = row * ASTRD + lane * 2;
        Ahp[jj] = h0; Ahp[jj + 1] = h1;
        Alp[jj] = l0; Alp[jj + 1] = l1;
    }
    __syncthreads();

    float acc[2][8][4];
    #pragma unroll
    for (int mt = 0; mt < 2; mt++)
        #pragma unroll
        for (int nt = 0; nt < 8; nt++)
            #pragma unroll
            for (int c = 0; c < 4; c++) acc[mt][nt][c] = 0.f;

    #pragma unroll 1
    for (int ch = 0; ch < 8; ch++) {
        int cur = ch & 1;
        CP_WAIT(0);
        __syncthreads();
        if (ch + 1 < 8)
            loadB_chunk(sh_base + BOFF + (uint32_t)(cur ^ 1) * 2 * PLANE * 4,
                        tid, WH, WL, (ch + 1) * 32, 128);
        CP_COMMIT();
        mma_chunkA(acc, sh_base + (uint32_t)(ch & 3) * 16 * 4,
                   sh_base + BOFF + (uint32_t)cur * 2 * PLANE * 4, wm, wn, lane);
        if (ch == 3) {
            __syncthreads();   // all MMAs on agg half done; reload planes with xin
            #pragma unroll 1
            for (int it = 0; it < 16; it++) {
                int row = wid * 16 + it;
                int node = n0 + row;
                float4 v = make_float4(0.f, 0.f, 0.f, 0.f);
                if (node < NN) v = *(const float4*)(xin + (size_t)node * HH + lane * 4);
                unsigned h0, l0, h1, l1;
                cvt_hilo(v.x, v.y, h0, l0);
                cvt_hilo(v.z, v.w, h1, l1);
                int jj = row * ASTRD + lane * 2;
                Ahp[jj] = h0; Ahp[jj + 1] = h1;
                Alp[jj] = l0; Alp[jj + 1] = l1;
            }
            __syncthreads();
        }
    }
    __syncthreads();

    // ---- epilogue: bias -> LN -> ReLU -> residual ----
    float* red_s = red;            // [2][128]
    float* red_q = red + 256;      // [2][128]
    int cbase = wn * 64 + (lane & 3) * 2;
    float bb[8][2], gg[8][2], be[8][2];
    #pragma unroll
    for (int nt = 0; nt < 8; nt++) {
        int col = cbase + nt * 8;
        bb[nt][0] = bias[col];  bb[nt][1] = bias[col + 1];
        gg[nt][0] = gamma[col]; gg[nt][1] = gamma[col + 1];
        be[nt][0] = beta[col];  be[nt][1] = beta[col + 1];
    }
    #pragma unroll
    for (int mt = 0; mt < 2; mt++)
        #pragma unroll
        for (int rr = 0; rr < 2; rr++) {
            float s = 0.f, q2 = 0.f;
            #pragma unroll
            for (int nt = 0; nt < 8; nt++)
                #pragma unroll
                for (int q = 0; q < 2; q++) {
                    float v = acc[mt][nt][rr * 2 + q] + bb[nt][q];
                    acc[mt][nt][rr * 2 + q] = v;
                    s += v; q2 += v * v;
                }
            s  += __shfl_xor_sync(0xffffffffu, s, 1);
            s  += __shfl_xor_sync(0xffffffffu, s, 2);
            q2 += __shfl_xor_sync(0xffffffffu, q2, 1);
            q2 += __shfl_xor_sync(0xffffffffu, q2, 2);
            if ((lane & 3) == 0) {
                int rb = wm * 32 + mt * 16 + rr * 8 + (lane >> 2);
                red_s[wn * 128 + rb] = s; red_q[wn * 128 + rb] = q2;
            }
        }
    __syncthreads();
    const float inv128 = 1.0f / 128.0f;
    #pragma unroll
    for (int mt = 0; mt < 2; mt++)
        #pragma unroll
        for (int rr = 0; rr < 2; rr++) {
            int rb = wm * 32 + mt * 16 + rr * 8 + (lane >> 2);
            int n = n0 + rb;
            float S = red_s[rb] + red_s[128 + rb];
            float Q = red_q[rb] + red_q[128 + rb];
            float mu = S * inv128;
            float var = Q * inv128 - mu * mu;
            float rs = rsqrtf(var + 1e-5f);
            if (n < NN) {
                #pragma unroll
                for (int nt = 0; nt < 8; nt++) {
                    int col = cbase + nt * 8;
                    float y0 = (acc[mt][nt][rr*2+0] - mu) * rs * gg[nt][0] + be[nt][0];
                    float y1 = (acc[mt][nt][rr*2+1] - mu) * rs * gg[nt][1] + be[nt][1];
                    y0 = fmaxf(y0, 0.f); y1 = fmaxf(y1, 0.f);
                    if (layer > 0) {
                        float2 rv = *(const float2*)(xin + (size_t)n * HH + col);
                        y0 += rv.x; y1 += rv.y;
                    }
                    *(float2*)(xout + (size_t)n * HH + col) = make_float2(y0, y1);
                }
            }
        }
}

// ---------------- JK head: K=512 tensor-core GEMM + bias -------------------
__global__ __launch_bounds__(256) void jk_k(
    const float* __restrict__ emb, const float* __restrict__ jkb,
    float* __restrict__ out) {
    extern __shared__ unsigned smem_u[];
    int tid = threadIdx.x, wid = tid >> 5, lane = tid & 31;
    int wm = wid & 3, wn = wid >> 2;
    int n0 = blockIdx.x * 128;
    int arow = tid >> 1, half = tid & 1;
    uint32_t sh_base = (uint32_t)__cvta_generic_to_shared(smem_u);
    const unsigned* WH = (const unsigned*)g_jkWb[0];
    const unsigned* WL = (const unsigned*)g_jkWb[1];

    float acc[2][8][4];
    #pragma unroll
    for (int mt = 0; mt < 2; mt++)
        #pragma unroll
        for (int nt = 0; nt < 8; nt++)
            #pragma unroll
            for (int c = 0; c < 4; c++) acc[mt][nt][c] = 0.f;

    float4 va[4];
    int nrow = n0 + arow;
    auto loadA = [&](int ch) {
        const float* base = (ch < 4) ? emb : g_xs[(ch >> 2) - 1];
        const float* srcp = base + (size_t)nrow * HH + (ch & 3) * 32;
        #pragma unroll
        for (int t = 0; t < 4; t++) {
            va[t] = make_float4(0.f, 0.f, 0.f, 0.f);
            if (nrow < NN) va[t] = *(const float4*)(srcp + half * 16 + t * 4);
        }
    };

    loadA(0);
    loadB_chunk(sh_base + 2u * PLANE * 4, tid, WH, WL, 0, 256);
    CP_COMMIT();
    #pragma unroll 2
    for (int ch = 0; ch < 16; ch++) {
        int cur = ch & 1;
        storeA(smem_u, cur, arow, half, va);
        if (ch + 1 < 16) {
            loadA(ch + 1);
            loadB_chunk(sh_base + ((uint32_t)(cur ^ 1) * 4 + 2) * PLANE * 4,
                        tid, WH, WL, (ch + 1) * 32, 256);
            CP_COMMIT();
            CP_WAIT(1);
        } else {
            CP_WAIT(0);
        }
        __syncthreads();
        mma_chunk(acc, sh_base, cur, wm, wn, lane);
        __syncthreads();
    }

    int cbase = wn * 64 + (lane & 3) * 2;
    float bb[8][2];
    #pragma unroll
    for (int nt = 0; nt < 8; nt++) {
        int col = cbase + nt * 8;
        bb[nt][0] = jkb[col]; bb[nt][1] = jkb[col + 1];
    }
    #pragma unroll
    for (int mt = 0; mt < 2; mt++)
        #pragma unroll
        for (int rr = 0; rr < 2; rr++) {
            int rb = wm * 32 + mt * 16 + rr * 8 + (lane >> 2);
            int n = n0 + rb;
            if (n < NN) {
                #pragma unroll
                for (int nt = 0; nt < 8; nt++) {
                    int col = cbase + nt * 8;
                    *(float2*)(out + (size_t)n * HH + col) =
                        make_float2(acc[mt][nt][rr*2+0] + bb[nt][0],
                                    acc[mt][nt][rr*2+1] + bb[nt][1]);
                }
            }
        }
}

// ---------------- launch ----------------------------------------------------
extern "C" void kernel_launch(void* const* d_in, const int* in_sizes, int n_in,
                              void* d_out, int out_size) {
    const float* emb   = (const float*)d_in[0];
    const float* Wl    = (const float*)d_in[1];
    const float* bl    = (const float*)d_in[2];
    const float* Wr    = (const float*)d_in[3];
    const float* gamma = (const float*)d_in[4];
    const float* beta  = (const float*)d_in[5];
    const float* jkW   = (const float*)d_in[6];
    const float* jkb   = (const float*)d_in[7];
    const int*   eidx  = (const int*)d_in[8];
    const int* src = eidx;
    const int* dst = eidx + NE;
    float* out = (float*)d_out;

    // layer kernel smem: A planes (2*128*ASTRD) + B double-buffer (4*PLANE) + red
    const int SM_LAYER = (2 * 128 * ASTRD + 4 * PLANE + 512) * 4;   // 112,640 B
    const int SM_JK    = 8 * PLANE * 4 + 4 * 512;                   // 83,968 B
    static bool attr_set = false;
    if (!attr_set) {
        cudaFuncSetAttribute(sage_layer_k, cudaFuncAttributeMaxDynamicSharedMemorySize, SM_LAYER);
        cudaFuncSetAttribute(jk_k,         cudaFuncAttributeMaxDynamicSharedMemorySize, SM_JK);
        attr_set = true;
    }

    const int initN = NL * 128 * 256 + 128 * 512;   // 163840 > NN
    init_k<<<(initN + 255) / 256, 256>>>(Wl, Wr, jkW);
    count_k<<<(NE + 255) / 256, 256>>>(dst);
    scan_k<<<NB, 1024>>>();
    fill_k<<<(NE + 255) / 256, 256>>>(src, dst);

    const int GB = (NN + 127) / 128;   // 782
    for (int l = 0; l < NL; l++)
        sage_layer_k<<<GB, 256, SM_LAYER>>>(emb, l, bl, gamma, beta);
    jk_k<<<GB, 256, SM_JK>>>(emb, jkb, out);
}

// round 9
// speedup vs baseline: 1.2539x; 1.2539x over previous
#include <cuda_runtime.h>
#include <cuda_bf16.h>
#include <stdint.h>

#define NN 100000
#define HH 128
#define NE 1600000
#define NL 3
#define NB 98   // scan blocks = ceil(NN/1024)

#define STRD 20              // smem row stride in 32-bit words (ldmatrix conflict-free)
#define PLANE (128 * STRD)   // one 128-row plane, in words

// ---------------- scratch (device globals) ----------------------------------
__device__ int   g_cnt[NN];
__device__ int   g_rowptr[NN + 1];
__device__ int   g_cursor[NN];
__device__ int   g_csr[NE];
__device__ int   g_state[NB];
__device__ int   g_aggv[NB];
__device__ int   g_prefv[NB];
__device__ float g_invdeg[NN];
__device__ float g_agg[(size_t)NN * HH];
__device__ float g_xs[NL][(size_t)NN * HH];
// bf16 copies of gather sources: [0]=emb, [1]=x0, [2]=x1
__device__ __nv_bfloat16 g_xb[NL][(size_t)NN * HH];
// weights pre-split to bf16 hi/lo, layout [h][k] (k contiguous)
__device__ __nv_bfloat16 g_Wb[NL][2][128 * 256];
__device__ __nv_bfloat16 g_jkWb[2][128 * 512];

// ---------------- helpers ----------------------------------------------------
__device__ __forceinline__ void cvt_hilo(float x, float y, unsigned& hi, unsigned& lo) {
    __nv_bfloat162 h = __floats2bfloat162_rn(x, y);
    float hx = __bfloat162float(h.x), hy = __bfloat162float(h.y);
    __nv_bfloat162 l = __floats2bfloat162_rn(x - hx, y - hy);
    hi = *reinterpret_cast<unsigned*>(&h);
    lo = *reinterpret_cast<unsigned*>(&l);
}

#define MMA16816(d, a, b) asm volatile( \
    "mma.sync.aligned.m16n8k16.row.col.f32.bf16.bf16.f32 " \
    "{%0,%1,%2,%3}, {%4,%5,%6,%7}, {%8,%9}, {%0,%1,%2,%3};" \
    : "+f"((d)[0]), "+f"((d)[1]), "+f"((d)[2]), "+f"((d)[3]) \
    : "r"((a)[0]), "r"((a)[1]), "r"((a)[2]), "r"((a)[3]), \
      "r"((b)[0]), "r"((b)[1]))

__device__ __forceinline__ void ldsm4(unsigned* r, uint32_t addr) {
    asm volatile("ldmatrix.sync.aligned.m8n8.x4.shared.b16 {%0,%1,%2,%3}, [%4];"
                 : "=r"(r[0]), "=r"(r[1]), "=r"(r[2]), "=r"(r[3]) : "r"(addr));
}

#define CP16(dst, src) asm volatile("cp.async.cg.shared.global [%0], [%1], 16;" :: "r"(dst), "l"(src))
#define CP_COMMIT()    asm volatile("cp.async.commit_group;")
#define CP_WAIT(n)     asm volatile("cp.async.wait_group %0;" :: "n"(n))

// ---------------- setup: zero counters/state + weight split -----------------
__global__ void init_k(const float* __restrict__ Wl, const float* __restrict__ Wr,
                       const float* __restrict__ jkW) {
    int i = blockIdx.x * blockDim.x + threadIdx.x;
    if (i < NN) { g_cnt[i] = 0; g_cursor[i] = 0; }
    if (i < NB) g_state[i] = 0;
    const int totW = NL * 128 * 256;
    float w; int dstl = -1, dsti = 0;
    if (i < totW) {
        int l = i >> 15;
        int rem = i & 32767;
        int h = rem >> 8, k = rem & 255;
        w = (k < 128) ? Wl[l * 16384 + h * 128 + k]
                      : Wr[l * 16384 + h * 128 + (k - 128)];
        dstl = l; dsti = rem;
    } else {
        int j = i - totW;
        if (j >= 128 * 512) return;
        w = jkW[j];
        dsti = j;
    }
    __nv_bfloat16 hi = __float2bfloat16(w);
    __nv_bfloat16 lo = __float2bfloat16(w - __bfloat162float(hi));
    if (dstl >= 0) { g_Wb[dstl][0][dsti] = hi; g_Wb[dstl][1][dsti] = lo; }
    else           { g_jkWb[0][dsti] = hi;     g_jkWb[1][dsti] = lo; }
}

// convert emb -> bf16 gather copy
__global__ void emb2bf_k(const float* __restrict__ emb) {
    size_t i = (size_t)(blockIdx.x * blockDim.x + threadIdx.x) * 2;
    if (i < (size_t)NN * HH) {
        float2 v = *(const float2*)(emb + i);
        *(__nv_bfloat162*)(&g_xb[0][i]) = __floats2bfloat162_rn(v.x, v.y);
    }
}

__global__ void count_k(const int* __restrict__ dst) {
    int i = blockIdx.x * blockDim.x + threadIdx.x;
    if (i < NE) atomicAdd(&g_cnt[dst[i]], 1);
}

// single-kernel decoupled-lookback exclusive scan (98 co-resident blocks)
__global__ void scan_k() {
    __shared__ int sh[1024];
    __shared__ int s_excl;
    int bid = blockIdx.x;
    int i = bid * 1024 + (int)threadIdx.x;
    int v = (i < NN) ? g_cnt[i] : 0;
    sh[threadIdx.x] = v;
    __syncthreads();
    #pragma unroll
    for (int off = 1; off < 1024; off <<= 1) {
        int t = (threadIdx.x >= (unsigned)off) ? sh[threadIdx.x - off] : 0;
        __syncthreads();
        sh[threadIdx.x] += t;
        __syncthreads();
    }
    int total = sh[1023];
    if (threadIdx.x == 0) {
        if (bid == 0) {
            g_prefv[0] = total;
            __threadfence();
            atomicExch(&g_state[0], 2);
            s_excl = 0;
        } else {
            g_aggv[bid] = total;
            __threadfence();
            atomicExch(&g_state[bid], 1);
            int excl = 0, j = bid - 1;
            while (j >= 0) {
                int st;
                do { st = atomicAdd(&g_state[j], 0); } while (st == 0);
                if (st == 2) { excl += atomicAdd(&g_prefv[j], 0); break; }
                excl += atomicAdd(&g_aggv[j], 0);
                j--;
            }
            g_prefv[bid] = excl + total;
            __threadfence();
            atomicExch(&g_state[bid], 2);
            s_excl = excl;
        }
    }
    __syncthreads();
    int excl = s_excl;
    if (i < NN) {
        g_rowptr[i] = sh[threadIdx.x] - v + excl;
        g_invdeg[i] = 1.0f / fmaxf((float)v, 1.0f);
    }
    if (bid == NB - 1 && threadIdx.x == 1023) g_rowptr[NN] = excl + total;
}

__global__ void fill_k(const int* __restrict__ src, const int* __restrict__ dst) {
    int i = blockIdx.x * blockDim.x + threadIdx.x;
    if (i < NE) {
        int d = dst[i];
        int pos = g_rowptr[d] + atomicAdd(&g_cursor[d], 1);
        g_csr[pos] = src[i];
    }
}

// ---------------- aggregation: one warp per node, bf16 gather, fp32 accum ---
__global__ void agg_k(int layer) {
    const __nv_bfloat16* __restrict__ x = g_xb[layer];
    int warp = (blockIdx.x * blockDim.x + threadIdx.x) >> 5;
    int lane = threadIdx.x & 31;
    if (warp >= NN) return;
    int beg = g_rowptr[warp], end = g_rowptr[warp + 1];
    const __nv_bfloat16* xb = x + lane * 4;
    float4 acc = make_float4(0.f, 0.f, 0.f, 0.f);
    int j = beg;
    for (; j + 3 < end; j += 4) {
        int s0 = g_csr[j], s1 = g_csr[j + 1], s2 = g_csr[j + 2], s3 = g_csr[j + 3];
        uint2 u0 = *(const uint2*)(xb + (size_t)s0 * HH);
        uint2 u1 = *(const uint2*)(xb + (size_t)s1 * HH);
        uint2 u2 = *(const uint2*)(xb + (size_t)s2 * HH);
        uint2 u3 = *(const uint2*)(xb + (size_t)s3 * HH);
        #pragma unroll
        for (int q = 0; q < 4; q++) {
            uint2 u = (q == 0) ? u0 : (q == 1) ? u1 : (q == 2) ? u2 : u3;
            float2 f0 = __bfloat1622float2(*(const __nv_bfloat162*)&u.x);
            float2 f1 = __bfloat1622float2(*(const __nv_bfloat162*)&u.y);
            acc.x += f0.x; acc.y += f0.y; acc.z += f1.x; acc.w += f1.y;
        }
    }
    for (; j < end; j++) {
        int s0 = g_csr[j];
        uint2 u = *(const uint2*)(xb + (size_t)s0 * HH);
        float2 f0 = __bfloat1622float2(*(const __nv_bfloat162*)&u.x);
        float2 f1 = __bfloat1622float2(*(const __nv_bfloat162*)&u.y);
        acc.x += f0.x; acc.y += f0.y; acc.z += f1.x; acc.w += f1.y;
    }
    float inv = g_invdeg[warp];
    acc.x *= inv; acc.y *= inv; acc.z *= inv; acc.w *= inv;
    *(float4*)(g_agg + (size_t)warp * HH + lane * 4) = acc;
}

// ---------------- shared GEMM machinery -------------------------------------
struct Frag { unsigned aH0[4], aL0[4], aH1[4], aL1[4], bh[8][2], bl[8][2]; };

__device__ __forceinline__ void mma_chunk(
    float acc[2][8][4], uint32_t sh_base, int cur, int wm, int wn, int lane) {
    int lr = lane & 7, lg8 = ((lane >> 3) & 1) * 8, lk4 = ((lane >> 4) & 1) * 4;
    uint32_t base = sh_base + (uint32_t)cur * 4 * PLANE * 4;
    uint32_t rowA = (uint32_t)(wm * 32 + lg8 + lr) * (STRD * 4);
    uint32_t rowB0 = (uint32_t)(wn * 64 + lg8 + lr) * (STRD * 4);
    #pragma unroll
    for (int s = 0; s < 2; s++) {
        uint32_t kb = (uint32_t)(s * 8 + lk4) * 4;
        Frag f;
        ldsm4(f.aH0, base + rowA + kb);
        ldsm4(f.aH1, base + rowA + 16 * (STRD * 4) + kb);
        ldsm4(f.aL0, base + PLANE * 4 + rowA + kb);
        ldsm4(f.aL1, base + PLANE * 4 + rowA + 16 * (STRD * 4) + kb);
        #pragma unroll
        for (int nt2 = 0; nt2 < 4; nt2++) {
            unsigned t[4];
            uint32_t rb = rowB0 + (uint32_t)(nt2 * 16) * (STRD * 4) + kb;
            ldsm4(t, base + 2 * PLANE * 4 + rb);
            f.bh[2*nt2][0] = t[0]; f.bh[2*nt2+1][0] = t[1];
            f.bh[2*nt2][1] = t[2]; f.bh[2*nt2+1][1] = t[3];
            ldsm4(t, base + 3 * PLANE * 4 + rb);
            f.bl[2*nt2][0] = t[0]; f.bl[2*nt2+1][0] = t[1];
            f.bl[2*nt2][1] = t[2]; f.bl[2*nt2+1][1] = t[3];
        }
        #pragma unroll
        for (int mt = 0; mt < 2; mt++) {
            const unsigned* aH = mt ? f.aH1 : f.aH0;
            const unsigned* aL = mt ? f.aL1 : f.aL0;
            #pragma unroll
            for (int nt = 0; nt < 8; nt++) {
                MMA16816(acc[mt][nt], aH, f.bh[nt]);
                MMA16816(acc[mt][nt], aH, f.bl[nt]);
                MMA16816(acc[mt][nt], aL, f.bh[nt]);
            }
        }
    }
}

// store staged A regs (16 floats) into smem hi/lo planes with cvt
__device__ __forceinline__ void storeA(unsigned* smem_u, int cur, int arow, int half,
                                       const float4 va[4]) {
    unsigned* Ah = smem_u + (size_t)cur * 4 * PLANE;
    unsigned* Al = Ah + PLANE;
    #pragma unroll
    for (int t = 0; t < 4; t++) {
        unsigned h0, l0, h1, l1;
        cvt_hilo(va[t].x, va[t].y, h0, l0);
        cvt_hilo(va[t].z, va[t].w, h1, l1);
        int j = arow * STRD + half * 8 + t * 2;
        Ah[j] = h0; Ah[j + 1] = h1;
        Al[j] = l0; Al[j + 1] = l1;
    }
}

// issue cp.async for B chunk (hi+lo planes) into buffer `buf`
__device__ __forceinline__ void loadB_async(uint32_t sh_base, int buf, int tid,
                                            const unsigned* WH, const unsigned* WL,
                                            int k0, int rowstride) {
    uint32_t bh_base = sh_base + ((uint32_t)buf * 4 * PLANE + 2 * PLANE) * 4;
    uint32_t bl_base = bh_base + PLANE * 4;
    #pragma unroll
    for (int it = 0; it < 2; it++) {
        int c = tid + it * 256;
        int row = c >> 2, part = c & 3;
        uint32_t doff = (uint32_t)(row * STRD + part * 4) * 4;
        const unsigned* sh = WH + (size_t)row * rowstride + (k0 >> 1) + part * 4;
        const unsigned* sl = WL + (size_t)row * rowstride + (k0 >> 1) + part * 4;
        CP16(bh_base + doff, sh);
        CP16(bl_base + doff, sl);
    }
}

// ---------------- fused GEMM (K=256) + bias + LN + ReLU + residual ---------
__global__ __launch_bounds__(256) void gemm_ln_k(
    const float* __restrict__ emb, int layer,
    const float* __restrict__ bl_all,
    const float* __restrict__ gamma_all, const float* __restrict__ beta_all) {
    extern __shared__ unsigned smem_u[];
    float* red = (float*)(smem_u + 8 * PLANE);   // red_s[2][128], red_q[2][128]

    const float* __restrict__ xin = (layer == 0) ? emb : g_xs[layer - 1];
    float* __restrict__ xout = g_xs[layer];
    __nv_bfloat16* __restrict__ xout_b = (layer < NL - 1) ? g_xb[layer + 1] : (__nv_bfloat16*)0;
    const unsigned* WH = (const unsigned*)g_Wb[layer][0];
    const unsigned* WL = (const unsigned*)g_Wb[layer][1];
    const float* __restrict__ bias  = bl_all + layer * 128;
    const float* __restrict__ gamma = gamma_all + layer * 128;
    const float* __restrict__ beta  = beta_all + layer * 128;

    int tid = threadIdx.x, wid = tid >> 5, lane = tid & 31;
    int wm = wid & 3, wn = wid >> 2;
    int n0 = blockIdx.x * 128;
    int arow = tid >> 1, half = tid & 1;
    uint32_t sh_base = (uint32_t)__cvta_generic_to_shared(smem_u);

    float acc[2][8][4];
    #pragma unroll
    for (int mt = 0; mt < 2; mt++)
        #pragma unroll
        for (int nt = 0; nt < 8; nt++)
            #pragma unroll
            for (int c = 0; c < 4; c++) acc[mt][nt][c] = 0.f;

    float4 va[4];
    int nrow = n0 + arow;
    auto loadA = [&](int ch) {
        int k0 = ch * 32;
        const float* srcp = (k0 < HH) ? (g_agg + (size_t)nrow * HH + k0)
                                      : (xin + (size_t)nrow * HH + (k0 - HH));
        #pragma unroll
        for (int t = 0; t < 4; t++) {
            va[t] = make_float4(0.f, 0.f, 0.f, 0.f);
            if (nrow < NN) va[t] = *(const float4*)(srcp + half * 16 + t * 4);
        }
    };

    loadA(0);
    loadB_async(sh_base, 0, tid, WH, WL, 0, 128);
    CP_COMMIT();
    #pragma unroll 2
    for (int ch = 0; ch < 8; ch++) {
        int cur = ch & 1;
        storeA(smem_u, cur, arow, half, va);
        if (ch + 1 < 8) {
            loadA(ch + 1);
            loadB_async(sh_base, cur ^ 1, tid, WH, WL, (ch + 1) * 32, 128);
            CP_COMMIT();
            CP_WAIT(1);
        } else {
            CP_WAIT(0);
        }
        __syncthreads();
        mma_chunk(acc, sh_base, cur, wm, wn, lane);
    }
    __syncthreads();

    // ---- epilogue: bias -> LN -> ReLU -> residual ----
    float* red_s = red;            // [2][128]
    float* red_q = red + 256;      // [2][128]
    int cbase = wn * 64 + (lane & 3) * 2;
    float bb[8][2], gg[8][2], be[8][2];
    #pragma unroll
    for (int nt = 0; nt < 8; nt++) {
        int col = cbase + nt * 8;
        bb[nt][0] = bias[col];  bb[nt][1] = bias[col + 1];
        gg[nt][0] = gamma[col]; gg[nt][1] = gamma[col + 1];
        be[nt][0] = beta[col];  be[nt][1] = beta[col + 1];
    }
    #pragma unroll
    for (int mt = 0; mt < 2; mt++)
        #pragma unroll
        for (int rr = 0; rr < 2; rr++) {
            float s = 0.f, q2 = 0.f;
            #pragma unroll
            for (int nt = 0; nt < 8; nt++)
                #pragma unroll
                for (int q = 0; q < 2; q++) {
                    float v = acc[mt][nt][rr * 2 + q] + bb[nt][q];
                    acc[mt][nt][rr * 2 + q] = v;
                    s += v; q2 += v * v;
                }
            s  += __shfl_xor_sync(0xffffffffu, s, 1);
            s  += __shfl_xor_sync(0xffffffffu, s, 2);
            q2 += __shfl_xor_sync(0xffffffffu, q2, 1);
            q2 += __shfl_xor_sync(0xffffffffu, q2, 2);
            if ((lane & 3) == 0) {
                int rb = wm * 32 + mt * 16 + rr * 8 + (lane >> 2);
                red_s[wn * 128 + rb] = s; red_q[wn * 128 + rb] = q2;
            }
        }
    __syncthreads();
    const float inv128 = 1.0f / 128.0f;
    #pragma unroll
    for (int mt = 0; mt < 2; mt++)
        #pragma unroll
        for (int rr = 0; rr < 2; rr++) {
            int rb = wm * 32 + mt * 16 + rr * 8 + (lane >> 2);
            int n = n0 + rb;
            float S = red_s[rb] + red_s[128 + rb];
            float Q = red_q[rb] + red_q[128 + rb];
            float mu = S * inv128;
            float var = Q * inv128 - mu * mu;
            float rs = rsqrtf(var + 1e-5f);
            if (n < NN) {
                #pragma unroll
                for (int nt = 0; nt < 8; nt++) {
                    int col = cbase + nt * 8;
                    float y0 = (acc[mt][nt][rr*2+0] - mu) * rs * gg[nt][0] + be[nt][0];
                    float y1 = (acc[mt][nt][rr*2+1] - mu) * rs * gg[nt][1] + be[nt][1];
                    y0 = fmaxf(y0, 0.f); y1 = fmaxf(y1, 0.f);
                    if (layer > 0) {
                        float2 rv = *(const float2*)(xin + (size_t)n * HH + col);
                        y0 += rv.x; y1 += rv.y;
                    }
                    *(float2*)(xout + (size_t)n * HH + col) = make_float2(y0, y1);
                    if (xout_b)
                        *(__nv_bfloat162*)(xout_b + (size_t)n * HH + col) =
                            __floats2bfloat162_rn(y0, y1);
                }
            }
        }
}

// ---------------- JK head: K=512 tensor-core GEMM + bias -------------------
__global__ __launch_bounds__(256) void jk_k(
    const float* __restrict__ emb, const float* __restrict__ jkb,
    float* __restrict__ out) {
    extern __shared__ unsigned smem_u[];
    int tid = threadIdx.x, wid = tid >> 5, lane = tid & 31;
    int wm = wid & 3, wn = wid >> 2;
    int n0 = blockIdx.x * 128;
    int arow = tid >> 1, half = tid & 1;
    uint32_t sh_base = (uint32_t)__cvta_generic_to_shared(smem_u);
    const unsigned* WH = (const unsigned*)g_jkWb[0];
    const unsigned* WL = (const unsigned*)g_jkWb[1];

    float acc[2][8][4];
    #pragma unroll
    for (int mt = 0; mt < 2; mt++)
        #pragma unroll
        for (int nt = 0; nt < 8; nt++)
            #pragma unroll
            for (int c = 0; c < 4; c++) acc[mt][nt][c] = 0.f;

    float4 va[4];
    int nrow = n0 + arow;
    auto loadA = [&](int ch) {
        const float* base = (ch < 4) ? emb : g_xs[(ch >> 2) - 1];
        const float* srcp = base + (size_t)nrow * HH + (ch & 3) * 32;
        #pragma unroll
        for (int t = 0; t < 4; t++) {
            va[t] = make_float4(0.f, 0.f, 0.f, 0.f);
            if (nrow < NN) va[t] = *(const float4*)(srcp + half * 16 + t * 4);
        }
    };

    loadA(0);
    loadB_async(sh_base, 0, tid, WH, WL, 0, 256);
    CP_COMMIT();
    #pragma unroll 2
    for (int ch = 0; ch < 16; ch++) {
        int cur = ch & 1;
        storeA(smem_u, cur, arow, half, va);
        if (ch + 1 < 16) {
            loadA(ch + 1);
            loadB_async(sh_base, cur ^ 1, tid, WH, WL, (ch + 1) * 32, 256);
            CP_COMMIT();
            CP_WAIT(1);
        } else {
            CP_WAIT(0);
        }
        __syncthreads();
        mma_chunk(acc, sh_base, cur, wm, wn, lane);
    }

    int cbase = wn * 64 + (lane & 3) * 2;
    float bb[8][2];
    #pragma unroll
    for (int nt = 0; nt < 8; nt++) {
        int col = cbase + nt * 8;
        bb[nt][0] = jkb[col]; bb[nt][1] = jkb[col + 1];
    }
    #pragma unroll
    for (int mt = 0; mt < 2; mt++)
        #pragma unroll
        for (int rr = 0; rr < 2; rr++) {
            int rb = wm * 32 + mt * 16 + rr * 8 + (lane >> 2);
            int n = n0 + rb;
            if (n < NN) {
                #pragma unroll
                for (int nt = 0; nt < 8; nt++) {
                    int col = cbase + nt * 8;
                    *(float2*)(out + (size_t)n * HH + col) =
                        make_float2(acc[mt][nt][rr*2+0] + bb[nt][0],
                                    acc[mt][nt][rr*2+1] + bb[nt][1]);
                }
            }
        }
}

// ---------------- launch ----------------------------------------------------
extern "C" void kernel_launch(void* const* d_in, const int* in_sizes, int n_in,
                              void* d_out, int out_size) {
    const float* emb   = (const float*)d_in[0];
    const float* Wl    = (const float*)d_in[1];
    const float* bl    = (const float*)d_in[2];
    const float* Wr    = (const float*)d_in[3];
    const float* gamma = (const float*)d_in[4];
    const float* beta  = (const float*)d_in[5];
    const float* jkW   = (const float*)d_in[6];
    const float* jkb   = (const float*)d_in[7];
    const int*   eidx  = (const int*)d_in[8];
    const int* src = eidx;
    const int* dst = eidx + NE;
    float* out = (float*)d_out;

    const int SMEMSZ = 8 * PLANE * 4 + 4 * 512;   // 81920 + 2048 = 83968 B
    static bool attr_set = false;
    if (!attr_set) {
        cudaFuncSetAttribute(gemm_ln_k, cudaFuncAttributeMaxDynamicSharedMemorySize, SMEMSZ);
        cudaFuncSetAttribute(jk_k,      cudaFuncAttributeMaxDynamicSharedMemorySize, SMEMSZ);
        attr_set = true;
    }

    const int initN = NL * 128 * 256 + 128 * 512;   // 163840 > NN
    init_k<<<(initN + 255) / 256, 256>>>(Wl, Wr, jkW);
    emb2bf_k<<<(NN * HH / 2 + 255) / 256, 256>>>(emb);
    count_k<<<(NE + 255) / 256, 256>>>(dst);
    scan_k<<<NB, 1024>>>();
    fill_k<<<(NE + 255) / 256, 256>>>(src, dst);

    const int GB = (NN + 127) / 128;   // 782
    for (int l = 0; l < NL; l++) {
        agg_k<<<(NN + 7) / 8, 256>>>(l);
        gemm_ln_k<<<GB, 256, SMEMSZ>>>(emb, l, bl, gamma, beta);
    }
    jk_k<<<GB, 256, SMEMSZ>>>(emb, jkb, out);
}

// round 11
// speedup vs baseline: 1.7965x; 1.4327x over previous
#include <cuda_runtime.h>
#include <cuda_fp16.h>
#include <stdint.h>

#define NN 100000
#define HH 128
#define NE 1600000
#define NL 3
#define NB 98   // scan blocks = ceil(NN/1024)

#define STRD 20              // smem row stride in 32-bit words (ldmatrix conflict-free)
#define PLANE (128 * STRD)   // one 128-row plane, in words
#define NPAD (NN + 128)      // padded rows so tail-block cp.async stays in bounds

// ---------------- scratch (device globals) ----------------------------------
__device__ int   g_cnt[NN];
__device__ int   g_rowptr[NN + 1];
__device__ int   g_cursor[NN];
__device__ int   g_csr[NE];
__device__ int   g_blksum[128];
__device__ float g_invdeg[NN];
__device__ float g_xs[NL][(size_t)NN * HH];          // fp32 activations (residual source)
__device__ __half g_aggh[(size_t)NPAD * HH];         // fp16 aggregation output (GEMM A)
__device__ __half g_xb[4][(size_t)NPAD * HH];        // fp16 copies: emb, x0, x1, x2
// weights fp16 hi/lo, layout [h][k] (k contiguous)
__device__ __half g_Wb[NL][2][128 * 256];
__device__ __half g_jkWb[2][128 * 512];

// ---------------- helpers ----------------------------------------------------
#define MMA16816(d, a, b) asm volatile( \
    "mma.sync.aligned.m16n8k16.row.col.f32.f16.f16.f32 " \
    "{%0,%1,%2,%3}, {%4,%5,%6,%7}, {%8,%9}, {%0,%1,%2,%3};" \
    : "+f"((d)[0]), "+f"((d)[1]), "+f"((d)[2]), "+f"((d)[3]) \
    : "r"((a)[0]), "r"((a)[1]), "r"((a)[2]), "r"((a)[3]), \
      "r"((b)[0]), "r"((b)[1]))

__device__ __forceinline__ void ldsm4(unsigned* r, uint32_t addr) {
    asm volatile("ldmatrix.sync.aligned.m8n8.x4.shared.b16 {%0,%1,%2,%3}, [%4];"
                 : "=r"(r[0]), "=r"(r[1]), "=r"(r[2]), "=r"(r[3]) : "r"(addr));
}

#define CP16(dst, src) asm volatile("cp.async.cg.shared.global [%0], [%1], 16;" :: "r"(dst), "l"(src))
#define CP_COMMIT()    asm volatile("cp.async.commit_group;")
#define CP_WAIT(n)     asm volatile("cp.async.wait_group %0;" :: "n"(n))

// ---------------- setup: zero counters + fp16 hi/lo weight split ------------
__global__ void init_k(const float* __restrict__ Wl, const float* __restrict__ Wr,
                       const float* __restrict__ jkW) {
    int i = blockIdx.x * blockDim.x + threadIdx.x;
    if (i < NN) { g_cnt[i] = 0; g_cursor[i] = 0; }
    const int totW = NL * 128 * 256;
    float w; int dstl = -1, dsti = 0;
    if (i < totW) {
        int l = i >> 15;
        int rem = i & 32767;
        int h = rem >> 8, k = rem & 255;
        w = (k < 128) ? Wl[l * 16384 + h * 128 + k]
                      : Wr[l * 16384 + h * 128 + (k - 128)];
        dstl = l; dsti = rem;
    } else {
        int j = i - totW;
        if (j >= 128 * 512) return;
        w = jkW[j];
        dsti = j;
    }
    __half hi = __float2half_rn(w);
    __half lo = __float2half_rn(w - __half2float(hi));
    if (dstl >= 0) { g_Wb[dstl][0][dsti] = hi; g_Wb[dstl][1][dsti] = lo; }
    else           { g_jkWb[0][dsti] = hi;     g_jkWb[1][dsti] = lo; }
}

// convert emb -> fp16 gather copy
__global__ void emb2h_k(const float* __restrict__ emb) {
    size_t i = (size_t)(blockIdx.x * blockDim.x + threadIdx.x) * 2;
    if (i < (size_t)NN * HH) {
        float2 v = *(const float2*)(emb + i);
        *(__half2*)(&g_xb[0][i]) = __floats2half2_rn(v.x, v.y);
    }
}

__global__ void count_k(const int* __restrict__ dst) {
    int i = blockIdx.x * blockDim.x + threadIdx.x;
    if (i < NE) atomicAdd(&g_cnt[dst[i]], 1);
}

// 3-phase scan (measured faster than decoupled lookback)
__global__ void scan1_k() {
    __shared__ int sh[1024];
    int i = blockIdx.x * 1024 + threadIdx.x;
    int v = (i < NN) ? g_cnt[i] : 0;
    sh[threadIdx.x] = v;
    __syncthreads();
    #pragma unroll
    for (int off = 1; off < 1024; off <<= 1) {
        int t = (threadIdx.x >= (unsigned)off) ? sh[threadIdx.x - off] : 0;
        __syncthreads();
        sh[threadIdx.x] += t;
        __syncthreads();
    }
    if (i < NN) {
        g_rowptr[i] = sh[threadIdx.x] - v;
        g_invdeg[i] = 1.0f / fmaxf((float)v, 1.0f);
    }
    if (threadIdx.x == 1023) g_blksum[blockIdx.x] = sh[1023];
}
__global__ void scan2_k() {
    __shared__ int sh[128];
    int t = threadIdx.x;
    int v = (t < NB) ? g_blksum[t] : 0;
    sh[t] = v;
    __syncthreads();
    #pragma unroll
    for (int off = 1; off < 128; off <<= 1) {
        int u = (t >= off) ? sh[t - off] : 0;
        __syncthreads();
        sh[t] += u;
        __syncthreads();
    }
    if (t < NB) g_blksum[t] = sh[t] - v;
    if (t == 127) g_rowptr[NN] = sh[127];
}
__global__ void scan3_k() {
    int i = blockIdx.x * 1024 + threadIdx.x;
    if (i < NN) g_rowptr[i] += g_blksum[blockIdx.x];
}

__global__ void fill_k(const int* __restrict__ src, const int* __restrict__ dst) {
    int i = blockIdx.x * blockDim.x + threadIdx.x;
    if (i < NE) {
        int d = dst[i];
        int pos = g_rowptr[d] + atomicAdd(&g_cursor[d], 1);
        g_csr[pos] = src[i];
    }
}

// ---------------- aggregation: 2 nodes/warp, 16 lanes each, uint4 loads -----
__global__ void agg_k(int layer) {
    const __half* __restrict__ x = g_xb[layer];
    int gid = blockIdx.x * blockDim.x + threadIdx.x;
    int warp = gid >> 5;
    int lane = threadIdx.x & 31;
    int sub = lane >> 4, ln = lane & 15;
    int node = warp * 2 + sub;
    if (node >= NN) return;
    int beg = g_rowptr[node], end = g_rowptr[node + 1];
    const __half* xb = x + ln * 8;
    float acc[8];
    #pragma unroll
    for (int t = 0; t < 8; t++) acc[t] = 0.f;
    int j = beg;
    for (; j + 3 < end; j += 4) {
        uint4 u[4];
        #pragma unroll
        for (int q = 0; q < 4; q++) {
            int s = g_csr[j + q];
            u[q] = *(const uint4*)(xb + (size_t)s * HH);
        }
        #pragma unroll
        for (int q = 0; q < 4; q++) {
            const __half2* h = (const __half2*)&u[q];
            #pragma unroll
            for (int t = 0; t < 4; t++) {
                float2 f = __half22float2(h[t]);
                acc[t * 2] += f.x; acc[t * 2 + 1] += f.y;
            }
        }
    }
    for (; j < end; j++) {
        int s = g_csr[j];
        uint4 uu = *(const uint4*)(xb + (size_t)s * HH);
        const __half2* h = (const __half2*)&uu;
        #pragma unroll
        for (int t = 0; t < 4; t++) {
            float2 f = __half22float2(h[t]);
            acc[t * 2] += f.x; acc[t * 2 + 1] += f.y;
        }
    }
    float inv = g_invdeg[node];
    __half2 o[4];
    #pragma unroll
    for (int t = 0; t < 4; t++)
        o[t] = __floats2half2_rn(acc[t * 2] * inv, acc[t * 2 + 1] * inv);
    *(uint4*)(g_aggh + (size_t)node * HH + ln * 8) = *(uint4*)o;
}

// ---------------- GEMM machinery --------------------------------------------
// buffer layout (words): buf b at b*3*PLANE: [A][Bh][Bl]; red floats after both bufs

// cp.async one 128x32-half tile into smem plane at dstBase
__device__ __forceinline__ void cp_tile(uint32_t dstBase, int tid,
                                        const __half* srcBase, int rowStride, int off) {
    #pragma unroll
    for (int it = 0; it < 2; it++) {
        int c = tid + it * 256;
        int row = c >> 2, part = c & 3;
        uint32_t d = dstBase + (uint32_t)(row * STRD + part * 4) * 4;
        const __half* s = srcBase + (size_t)row * rowStride + off + part * 8;
        CP16(d, s);
    }
}

// fp16 2-term MMA over one 32-k chunk
__device__ __forceinline__ void mma_chunk16(
    float acc[2][8][4], uint32_t sh_base, int cur, int wm, int wn, int lane) {
    int lr = lane & 7, lg8 = ((lane >> 3) & 1) * 8, lk4 = ((lane >> 4) & 1) * 4;
    uint32_t base = sh_base + (uint32_t)cur * 3 * PLANE * 4;
    uint32_t rowA = (uint32_t)(wm * 32 + lg8 + lr) * (STRD * 4);
    uint32_t rowB0 = (uint32_t)(wn * 64 + lg8 + lr) * (STRD * 4);
    #pragma unroll
    for (int s = 0; s < 2; s++) {
        uint32_t kb = (uint32_t)(s * 8 + lk4) * 4;
        unsigned a0[4], a1[4], bh[8][2], bl[8][2];
        ldsm4(a0, base + rowA + kb);
        ldsm4(a1, base + rowA + 16 * (STRD * 4) + kb);
        #pragma unroll
        for (int nt2 = 0; nt2 < 4; nt2++) {
            unsigned t[4];
            uint32_t rb = rowB0 + (uint32_t)(nt2 * 16) * (STRD * 4) + kb;
            ldsm4(t, base + PLANE * 4 + rb);
            bh[2*nt2][0] = t[0]; bh[2*nt2+1][0] = t[1];
            bh[2*nt2][1] = t[2]; bh[2*nt2+1][1] = t[3];
            ldsm4(t, base + 2 * PLANE * 4 + rb);
            bl[2*nt2][0] = t[0]; bl[2*nt2+1][0] = t[1];
            bl[2*nt2][1] = t[2]; bl[2*nt2+1][1] = t[3];
        }
        #pragma unroll
        for (int mt = 0; mt < 2; mt++) {
            const unsigned* a = mt ? a1 : a0;
            #pragma unroll
            for (int nt = 0; nt < 8; nt++) {
                MMA16816(acc[mt][nt], a, bh[nt]);
                MMA16816(acc[mt][nt], a, bl[nt]);
            }
        }
    }
}

// ---------------- fused GEMM (K=256) + bias + LN + ReLU + residual ---------
__global__ __launch_bounds__(256) void gemm_ln_k(
    int layer, const float* __restrict__ emb,
    const float* __restrict__ bl_all,
    const float* __restrict__ gamma_all, const float* __restrict__ beta_all) {
    extern __shared__ unsigned smem_u[];
    float* red = (float*)(smem_u + 6 * PLANE);   // red_s[2][128], red_q[2][128]

    const float* __restrict__ xin = (layer == 0) ? emb : g_xs[layer - 1];
    float* __restrict__ xout = g_xs[layer];
    __half* __restrict__ xout_h = g_xb[layer + 1];
    const __half* WH = g_Wb[layer][0];
    const __half* WL = g_Wb[layer][1];
    const float* __restrict__ bias  = bl_all + layer * 128;
    const float* __restrict__ gamma = gamma_all + layer * 128;
    const float* __restrict__ beta  = beta_all + layer * 128;

    int tid = threadIdx.x, wid = tid >> 5, lane = tid & 31;
    int wm = wid & 3, wn = wid >> 2;
    int n0 = blockIdx.x * 128;
    uint32_t sh_base = (uint32_t)__cvta_generic_to_shared(smem_u);
    const __half* aggBase = g_aggh + (size_t)n0 * HH;
    const __half* xbBase  = g_xb[layer] + (size_t)n0 * HH;

    float acc[2][8][4];
    #pragma unroll
    for (int mt = 0; mt < 2; mt++)
        #pragma unroll
        for (int nt = 0; nt < 8; nt++)
            #pragma unroll
            for (int c = 0; c < 4; c++) acc[mt][nt][c] = 0.f;

    auto issue = [&](int ch) {
        uint32_t b = sh_base + (uint32_t)(ch & 1) * 3 * PLANE * 4;
        int k0 = ch * 32;
        if (k0 < HH) cp_tile(b, tid, aggBase, HH, k0);
        else         cp_tile(b, tid, xbBase,  HH, k0 - HH);
        cp_tile(b + PLANE * 4,     tid, WH, 256, k0);
        cp_tile(b + 2 * PLANE * 4, tid, WL, 256, k0);
    };

    issue(0);
    CP_COMMIT();
    #pragma unroll 1
    for (int ch = 0; ch < 8; ch++) {
        if (ch + 1 < 8) { issue(ch + 1); CP_COMMIT(); CP_WAIT(1); }
        else            { CP_WAIT(0); }
        __syncthreads();
        mma_chunk16(acc, sh_base, ch & 1, wm, wn, lane);
        __syncthreads();
    }

    // ---- epilogue: bias -> LN -> ReLU -> residual ----
    float* red_s = red;            // [2][128]
    float* red_q = red + 256;      // [2][128]
    int cbase = wn * 64 + (lane & 3) * 2;
    float bb[8][2], gg[8][2], be[8][2];
    #pragma unroll
    for (int nt = 0; nt < 8; nt++) {
        int col = cbase + nt * 8;
        bb[nt][0] = bias[col];  bb[nt][1] = bias[col + 1];
        gg[nt][0] = gamma[col]; gg[nt][1] = gamma[col + 1];
        be[nt][0] = beta[col];  be[nt][1] = beta[col + 1];
    }
    #pragma unroll
    for (int mt = 0; mt < 2; mt++)
        #pragma unroll
        for (int rr = 0; rr < 2; rr++) {
            float s = 0.f, q2 = 0.f;
            #pragma unroll
            for (int nt = 0; nt < 8; nt++)
                #pragma unroll
                for (int q = 0; q < 2; q++) {
                    float v = acc[mt][nt][rr * 2 + q] + bb[nt][q];
                    acc[mt][nt][rr * 2 + q] = v;
                    s += v; q2 += v * v;
                }
            s  += __shfl_xor_sync(0xffffffffu, s, 1);
            s  += __shfl_xor_sync(0xffffffffu, s, 2);
            q2 += __shfl_xor_sync(0xffffffffu, q2, 1);
            q2 += __shfl_xor_sync(0xffffffffu, q2, 2);
            if ((lane & 3) == 0) {
                int rb = wm * 32 + mt * 16 + rr * 8 + (lane >> 2);
                red_s[wn * 128 + rb] = s; red_q[wn * 128 + rb] = q2;
            }
        }
    __syncthreads();
    const float inv128 = 1.0f / 128.0f;
    #pragma unroll
    for (int mt = 0; mt < 2; mt++)
        #pragma unroll
        for (int rr = 0; rr < 2; rr++) {
            int rb = wm * 32 + mt * 16 + rr * 8 + (lane >> 2);
            int n = n0 + rb;
            float S = red_s[rb] + red_s[128 + rb];
            float Q = red_q[rb] + red_q[128 + rb];
            float mu = S * inv128;
            float var = Q * inv128 - mu * mu;
            float rs = rsqrtf(var + 1e-5f);
            if (n < NN) {
                #pragma unroll
                for (int nt = 0; nt < 8; nt++) {
                    int col = cbase + nt * 8;
                    float y0 = (acc[mt][nt][rr*2+0] - mu) * rs * gg[nt][0] + be[nt][0];
                    float y1 = (acc[mt][nt][rr*2+1] - mu) * rs * gg[nt][1] + be[nt][1];
                    y0 = fmaxf(y0, 0.f); y1 = fmaxf(y1, 0.f);
                    if (layer > 0) {
                        float2 rv = *(const float2*)(xin + (size_t)n * HH + col);
                        y0 += rv.x; y1 += rv.y;
                    }
                    if (layer < NL - 1)
                        *(float2*)(xout + (size_t)n * HH + col) = make_float2(y0, y1);
                    *(__half2*)(xout_h + (size_t)n * HH + col) = __floats2half2_rn(y0, y1);
                }
            }
        }
}

// ---------------- JK head: K=512 fp16 GEMM + bias ---------------------------
__global__ __launch_bounds__(256) void jk_k(
    const float* __restrict__ jkb, float* __restrict__ out) {
    extern __shared__ unsigned smem_u[];
    int tid = threadIdx.x, wid = tid >> 5, lane = tid & 31;
    int wm = wid & 3, wn = wid >> 2;
    int n0 = blockIdx.x * 128;
    uint32_t sh_base = (uint32_t)__cvta_generic_to_shared(smem_u);
    const __half* WH = g_jkWb[0];
    const __half* WL = g_jkWb[1];

    float acc[2][8][4];
    #pragma unroll
    for (int mt = 0; mt < 2; mt++)
        #pragma unroll
        for (int nt = 0; nt < 8; nt++)
            #pragma unroll
            for (int c = 0; c < 4; c++) acc[mt][nt][c] = 0.f;

    auto issue = [&](int ch) {
        uint32_t b = sh_base + (uint32_t)(ch & 1) * 3 * PLANE * 4;
        const __half* As = g_xb[ch >> 2] + (size_t)n0 * HH;
        cp_tile(b, tid, As, HH, (ch & 3) * 32);
        int k0 = ch * 32;
        cp_tile(b + PLANE * 4,     tid, WH, 512, k0);
        cp_tile(b + 2 * PLANE * 4, tid, WL, 512, k0);
    };

    issue(0);
    CP_COMMIT();
    #pragma unroll 1
    for (int ch = 0; ch < 16; ch++) {
        if (ch + 1 < 16) { issue(ch + 1); CP_COMMIT(); CP_WAIT(1); }
        else             { CP_WAIT(0); }
        __syncthreads();
        mma_chunk16(acc, sh_base, ch & 1, wm, wn, lane);
        __syncthreads();
    }

    int cbase = wn * 64 + (lane & 3) * 2;
    float bb[8][2];
    #pragma unroll
    for (int nt = 0; nt < 8; nt++) {
        int col = cbase + nt * 8;
        bb[nt][0] = jkb[col]; bb[nt][1] = jkb[col + 1];
    }
    #pragma unroll
    for (int mt = 0; mt < 2; mt++)
        #pragma unroll
        for (int rr = 0; rr < 2; rr++) {
            int rb = wm * 32 + mt * 16 + rr * 8 + (lane >> 2);
            int n = n0 + rb;
            if (n < NN) {
                #pragma unroll
                for (int nt = 0; nt < 8; nt++) {
                    int col = cbase + nt * 8;
                    *(float2*)(out + (size_t)n * HH + col) =
                        make_float2(acc[mt][nt][rr*2+0] + bb[nt][0],
                                    acc[mt][nt][rr*2+1] + bb[nt][1]);
                }
            }
        }
}

// ---------------- launch ----------------------------------------------------
extern "C" void kernel_launch(void* const* d_in, const int* in_sizes, int n_in,
                              void* d_out, int out_size) {
    const float* emb   = (const float*)d_in[0];
    const float* Wl    = (const float*)d_in[1];
    const float* bl    = (const float*)d_in[2];
    const float* Wr    = (const float*)d_in[3];
    const float* gamma = (const float*)d_in[4];
    const float* beta  = (const float*)d_in[5];
    const float* jkW   = (const float*)d_in[6];
    const float* jkb   = (const float*)d_in[7];
    const int*   eidx  = (const int*)d_in[8];
    const int* src = eidx;
    const int* dst = eidx + NE;
    float* out = (float*)d_out;

    const int SMEMSZ = 6 * PLANE * 4 + 4 * 512;   // 61440 + 2048 = 63488 B
    static bool attr_set = false;
    if (!attr_set) {
        cudaFuncSetAttribute(gemm_ln_k, cudaFuncAttributeMaxDynamicSharedMemorySize, SMEMSZ);
        cudaFuncSetAttribute(jk_k,      cudaFuncAttributeMaxDynamicSharedMemorySize, SMEMSZ);
        attr_set = true;
    }

    const int initN = NL * 128 * 256 + 128 * 512;   // 163840 > NN
    init_k<<<(initN + 255) / 256, 256>>>(Wl, Wr, jkW);
    emb2h_k<<<(NN * HH / 2 + 255) / 256, 256>>>(emb);
    count_k<<<(NE + 255) / 256, 256>>>(dst);
    scan1_k<<<NB, 1024>>>();
    scan2_k<<<1, 128>>>();
    scan3_k<<<NB, 1024>>>();
    fill_k<<<(NE + 255) / 256, 256>>>(src, dst);

    const int GB = (NN + 127) / 128;   // 782
    for (int l = 0; l < NL; l++) {
        agg_k<<<(NN + 15) / 16, 256>>>(l);
        gemm_ln_k<<<GB, 256, SMEMSZ>>>(l, emb, bl, gamma, beta);
    }
    jk_k<<<GB, 256, SMEMSZ>>>(jkb, out);
}

// round 12
// speedup vs baseline: 1.9347x; 1.0769x over previous
#include <cuda_runtime.h>
#include <cuda_fp16.h>
#include <stdint.h>

#define NN 100000
#define HH 128
#define NE 1600000
#define NL 3
#define NB 98   // scan blocks = ceil(NN/1024)

#define STRD 20              // smem row stride in 32-bit words (ldmatrix conflict-free)
#define PLANE (128 * STRD)   // one 128-row plane, in words
#define NPAD (NN + 128)      // padded rows so tail-block cp.async stays in bounds

// ---------------- scratch (device globals) ----------------------------------
__device__ int   g_cnt[NN];
__device__ int   g_rowptr[NN + 1];   // per-block partial exclusive scan (+ g_blksum[b])
__device__ int   g_cursor[NN];
__device__ int   g_csr[NE];
__device__ int   g_blksum[128];
__device__ float g_invdeg[NN];
__device__ __half g_aggh[(size_t)NPAD * HH];   // fp16 aggregation output (GEMM A)
__device__ __half g_xb[4][(size_t)NPAD * HH];  // fp16 activations: emb, x0, x1, x2
// weights fp16 hi/lo, layout [h][k] (k contiguous)
__device__ __half g_Wb[NL][2][128 * 256];
__device__ __half g_jkWb[2][128 * 512];

// ---------------- helpers ----------------------------------------------------
#define MMA16816(d, a, b) asm volatile( \
    "mma.sync.aligned.m16n8k16.row.col.f32.f16.f16.f32 " \
    "{%0,%1,%2,%3}, {%4,%5,%6,%7}, {%8,%9}, {%0,%1,%2,%3};" \
    : "+f"((d)[0]), "+f"((d)[1]), "+f"((d)[2]), "+f"((d)[3]) \
    : "r"((a)[0]), "r"((a)[1]), "r"((a)[2]), "r"((a)[3]), \
      "r"((b)[0]), "r"((b)[1]))

__device__ __forceinline__ void ldsm4(unsigned* r, uint32_t addr) {
    asm volatile("ldmatrix.sync.aligned.m8n8.x4.shared.b16 {%0,%1,%2,%3}, [%4];"
                 : "=r"(r[0]), "=r"(r[1]), "=r"(r[2]), "=r"(r[3]) : "r"(addr));
}

#define CP16(dst, src) asm volatile("cp.async.cg.shared.global [%0], [%1], 16;" :: "r"(dst), "l"(src))
#define CP_COMMIT()    asm volatile("cp.async.commit_group;")
#define CP_WAIT(n)     asm volatile("cp.async.wait_group %0;" :: "n"(n))

// ---------------- setup: zero counters + weight split + emb->fp16 -----------
__global__ void init_k(const float* __restrict__ Wl, const float* __restrict__ Wr,
                       const float* __restrict__ jkW, const float* __restrict__ emb) {
    int i = blockIdx.x * blockDim.x + threadIdx.x;
    if (i < NN) { g_cnt[i] = 0; g_cursor[i] = 0; }
    const int totW = NL * 128 * 256;
    if (i < totW) {
        int l = i >> 15;
        int rem = i & 32767;
        int h = rem >> 8, k = rem & 255;
        float w = (k < 128) ? Wl[l * 16384 + h * 128 + k]
                            : Wr[l * 16384 + h * 128 + (k - 128)];
        __half hi = __float2half_rn(w);
        g_Wb[l][0][rem] = hi;
        g_Wb[l][1][rem] = __float2half_rn(w - __half2float(hi));
    } else if (i < totW + 128 * 512) {
        int j = i - totW;
        float w = jkW[j];
        __half hi = __float2half_rn(w);
        g_jkWb[0][j] = hi;
        g_jkWb[1][j] = __float2half_rn(w - __half2float(hi));
    }
    size_t p = (size_t)i * 2;
    if (p < (size_t)NN * HH) {
        float2 v = *(const float2*)(emb + p);
        *(__half2*)(&g_xb[0][p]) = __floats2half2_rn(v.x, v.y);
    }
}

__global__ void count_k(const int* __restrict__ dst) {
    int i = blockIdx.x * blockDim.x + threadIdx.x;
    if (i < NE) atomicAdd(&g_cnt[dst[i]], 1);
}

// scan phase 1: per-block exclusive scan + block totals (+ invdeg)
__global__ void scan1_k() {
    __shared__ int sh[1024];
    int i = blockIdx.x * 1024 + threadIdx.x;
    int v = (i < NN) ? g_cnt[i] : 0;
    sh[threadIdx.x] = v;
    __syncthreads();
    #pragma unroll
    for (int off = 1; off < 1024; off <<= 1) {
        int t = (threadIdx.x >= (unsigned)off) ? sh[threadIdx.x - off] : 0;
        __syncthreads();
        sh[threadIdx.x] += t;
        __syncthreads();
    }
    if (i < NN) {
        g_rowptr[i] = sh[threadIdx.x] - v;
        g_invdeg[i] = 1.0f / fmaxf((float)v, 1.0f);
    }
    if (threadIdx.x == 1023) g_blksum[blockIdx.x] = sh[1023];
}
// scan phase 2: exclusive-scan block totals in place (consumers add inline)
__global__ void scan2_k() {
    __shared__ int sh[128];
    int t = threadIdx.x;
    int v = (t < NB) ? g_blksum[t] : 0;
    sh[t] = v;
    __syncthreads();
    #pragma unroll
    for (int off = 1; off < 128; off <<= 1) {
        int u = (t >= off) ? sh[t - off] : 0;
        __syncthreads();
        sh[t] += u;
        __syncthreads();
    }
    if (t < NB) g_blksum[t] = sh[t] - v;
    if (t == 127) g_rowptr[NN] = NE;   // total degree == edge count
}

__global__ void fill_k(const int* __restrict__ src, const int* __restrict__ dst) {
    int i = blockIdx.x * blockDim.x + threadIdx.x;
    if (i < NE) {
        int d = dst[i];
        int pos = g_rowptr[d] + g_blksum[d >> 10] + atomicAdd(&g_cursor[d], 1);
        g_csr[pos] = src[i];
    }
}

// ---------------- aggregation: 2 nodes/warp, 16 lanes each, uint4 loads -----
__global__ void agg_k(int layer) {
    const __half* __restrict__ x = g_xb[layer];
    int gid = blockIdx.x * blockDim.x + threadIdx.x;
    int warp = gid >> 5;
    int lane = threadIdx.x & 31;
    int sub = lane >> 4, ln = lane & 15;
    int node = warp * 2 + sub;
    if (node >= NN) return;
    int beg = g_rowptr[node] + g_blksum[node >> 10];
    int end = (node + 1 < NN) ? (g_rowptr[node + 1] + g_blksum[(node + 1) >> 10]) : NE;
    const __half* xb = x + ln * 8;
    float acc[8];
    #pragma unroll
    for (int t = 0; t < 8; t++) acc[t] = 0.f;
    int j = beg;
    for (; j + 3 < end; j += 4) {
        uint4 u[4];
        #pragma unroll
        for (int q = 0; q < 4; q++) {
            int s = g_csr[j + q];
            u[q] = *(const uint4*)(xb + (size_t)s * HH);
        }
        #pragma unroll
        for (int q = 0; q < 4; q++) {
            const __half2* h = (const __half2*)&u[q];
            #pragma unroll
            for (int t = 0; t < 4; t++) {
                float2 f = __half22float2(h[t]);
                acc[t * 2] += f.x; acc[t * 2 + 1] += f.y;
            }
        }
    }
    for (; j < end; j++) {
        int s = g_csr[j];
        uint4 uu = *(const uint4*)(xb + (size_t)s * HH);
        const __half2* h = (const __half2*)&uu;
        #pragma unroll
        for (int t = 0; t < 4; t++) {
            float2 f = __half22float2(h[t]);
            acc[t * 2] += f.x; acc[t * 2 + 1] += f.y;
        }
    }
    float inv = g_invdeg[node];
    __half2 o[4];
    #pragma unroll
    for (int t = 0; t < 4; t++)
        o[t] = __floats2half2_rn(acc[t * 2] * inv, acc[t * 2 + 1] * inv);
    *(uint4*)(g_aggh + (size_t)node * HH + ln * 8) = *(uint4*)o;
}

// ---------------- GEMM machinery --------------------------------------------
// buffer layout (words): buf b at b*3*PLANE: [A][Bh][Bl]; red floats after both bufs

// cp.async one 128x32-half tile into smem plane at dstBase
__device__ __forceinline__ void cp_tile(uint32_t dstBase, int tid,
                                        const __half* srcBase, int rowStride, int off) {
    #pragma unroll
    for (int it = 0; it < 2; it++) {
        int c = tid + it * 256;
        int row = c >> 2, part = c & 3;
        uint32_t d = dstBase + (uint32_t)(row * STRD + part * 4) * 4;
        const __half* s = srcBase + (size_t)row * rowStride + off + part * 8;
        CP16(d, s);
    }
}

// fp16 2-term MMA over one 32-k chunk
__device__ __forceinline__ void mma_chunk16(
    float acc[2][8][4], uint32_t sh_base, int cur, int wm, int wn, int lane) {
    int lr = lane & 7, lg8 = ((lane >> 3) & 1) * 8, lk4 = ((lane >> 4) & 1) * 4;
    uint32_t base = sh_base + (uint32_t)cur * 3 * PLANE * 4;
    uint32_t rowA = (uint32_t)(wm * 32 + lg8 + lr) * (STRD * 4);
    uint32_t rowB0 = (uint32_t)(wn * 64 + lg8 + lr) * (STRD * 4);
    #pragma unroll
    for (int s = 0; s < 2; s++) {
        uint32_t kb = (uint32_t)(s * 8 + lk4) * 4;
        unsigned a0[4], a1[4], bh[8][2], bl[8][2];
        ldsm4(a0, base + rowA + kb);
        ldsm4(a1, base + rowA + 16 * (STRD * 4) + kb);
        #pragma unroll
        for (int nt2 = 0; nt2 < 4; nt2++) {
            unsigned t[4];
            uint32_t rb = rowB0 + (uint32_t)(nt2 * 16) * (STRD * 4) + kb;
            ldsm4(t, base + PLANE * 4 + rb);
            bh[2*nt2][0] = t[0]; bh[2*nt2+1][0] = t[1];
            bh[2*nt2][1] = t[2]; bh[2*nt2+1][1] = t[3];
            ldsm4(t, base + 2 * PLANE * 4 + rb);
            bl[2*nt2][0] = t[0]; bl[2*nt2+1][0] = t[1];
            bl[2*nt2][1] = t[2]; bl[2*nt2+1][1] = t[3];
        }
        #pragma unroll
        for (int mt = 0; mt < 2; mt++) {
            const unsigned* a = mt ? a1 : a0;
            #pragma unroll
            for (int nt = 0; nt < 8; nt++) {
                MMA16816(acc[mt][nt], a, bh[nt]);
                MMA16816(acc[mt][nt], a, bl[nt]);
            }
        }
    }
}

// ---------------- fused GEMM (K=256) + bias + LN + ReLU + residual ---------
__global__ __launch_bounds__(256) void gemm_ln_k(
    int layer,
    const float* __restrict__ bl_all,
    const float* __restrict__ gamma_all, const float* __restrict__ beta_all) {
    extern __shared__ unsigned smem_u[];
    float* red = (float*)(smem_u + 6 * PLANE);   // red_s[2][128], red_q[2][128]

    const __half* __restrict__ xin_h = g_xb[layer];
    __half* __restrict__ xout_h = g_xb[layer + 1];
    const __half* WH = g_Wb[layer][0];
    const __half* WL = g_Wb[layer][1];
    const float* __restrict__ bias  = bl_all + layer * 128;
    const float* __restrict__ gamma = gamma_all + layer * 128;
    const float* __restrict__ beta  = beta_all + layer * 128;

    int tid = threadIdx.x, wid = tid >> 5, lane = tid & 31;
    int wm = wid & 3, wn = wid >> 2;
    int n0 = blockIdx.x * 128;
    uint32_t sh_base = (uint32_t)__cvta_generic_to_shared(smem_u);
    const __half* aggBase = g_aggh + (size_t)n0 * HH;
    const __half* xbBase  = xin_h + (size_t)n0 * HH;

    float acc[2][8][4];
    #pragma unroll
    for (int mt = 0; mt < 2; mt++)
        #pragma unroll
        for (int nt = 0; nt < 8; nt++)
            #pragma unroll
            for (int c = 0; c < 4; c++) acc[mt][nt][c] = 0.f;

    auto issue = [&](int ch) {
        uint32_t b = sh_base + (uint32_t)(ch & 1) * 3 * PLANE * 4;
        int k0 = ch * 32;
        if (k0 < HH) cp_tile(b, tid, aggBase, HH, k0);
        else         cp_tile(b, tid, xbBase,  HH, k0 - HH);
        cp_tile(b + PLANE * 4,     tid, WH, 256, k0);
        cp_tile(b + 2 * PLANE * 4, tid, WL, 256, k0);
    };

    issue(0);
    CP_COMMIT();
    // single-sync pipeline: loads for ch+1 overlap mma(ch); top sync guards
    // both cross-thread cp.async visibility (ch, waited below last iter) and
    // buffer reuse (mma(ch-1) done before issue(ch+1) overwrites its buffer).
    #pragma unroll 1
    for (int ch = 0; ch < 8; ch++) {
        CP_WAIT(0);
        __syncthreads();
        if (ch + 1 < 8) { issue(ch + 1); CP_COMMIT(); }
        mma_chunk16(acc, sh_base, ch & 1, wm, wn, lane);
        __syncthreads();
    }

    // ---- epilogue: bias -> LN -> ReLU -> residual(fp16) ----
    float* red_s = red;            // [2][128]
    float* red_q = red + 256;      // [2][128]
    int cbase = wn * 64 + (lane & 3) * 2;
    float bb[8][2], gg[8][2], be[8][2];
    #pragma unroll
    for (int nt = 0; nt < 8; nt++) {
        int col = cbase + nt * 8;
        bb[nt][0] = bias[col];  bb[nt][1] = bias[col + 1];
        gg[nt][0] = gamma[col]; gg[nt][1] = gamma[col + 1];
        be[nt][0] = beta[col];  be[nt][1] = beta[col + 1];
    }
    #pragma unroll
    for (int mt = 0; mt < 2; mt++)
        #pragma unroll
        for (int rr = 0; rr < 2; rr++) {
            float s = 0.f, q2 = 0.f;
            #pragma unroll
            for (int nt = 0; nt < 8; nt++)
                #pragma unroll
                for (int q = 0; q < 2; q++) {
                    float v = acc[mt][nt][rr * 2 + q] + bb[nt][q];
                    acc[mt][nt][rr * 2 + q] = v;
                    s += v; q2 += v * v;
                }
            s  += __shfl_xor_sync(0xffffffffu, s, 1);
            s  += __shfl_xor_sync(0xffffffffu, s, 2);
            q2 += __shfl_xor_sync(0xffffffffu, q2, 1);
            q2 += __shfl_xor_sync(0xffffffffu, q2, 2);
            if ((lane & 3) == 0) {
                int rb = wm * 32 + mt * 16 + rr * 8 + (lane >> 2);
                red_s[wn * 128 + rb] = s; red_q[wn * 128 + rb] = q2;
            }
        }
    __syncthreads();
    const float inv128 = 1.0f / 128.0f;
    #pragma unroll
    for (int mt = 0; mt < 2; mt++)
        #pragma unroll
        for (int rr = 0; rr < 2; rr++) {
            int rb = wm * 32 + mt * 16 + rr * 8 + (lane >> 2);
            int n = n0 + rb;
            float S = red_s[rb] + red_s[128 + rb];
            float Q = red_q[rb] + red_q[128 + rb];
            float mu = S * inv128;
            float var = Q * inv128 - mu * mu;
            float rs = rsqrtf(var + 1e-5f);
            if (n < NN) {
                #pragma unroll
                for (int nt = 0; nt < 8; nt++) {
                    int col = cbase + nt * 8;
                    float y0 = (acc[mt][nt][rr*2+0] - mu) * rs * gg[nt][0] + be[nt][0];
                    float y1 = (acc[mt][nt][rr*2+1] - mu) * rs * gg[nt][1] + be[nt][1];
                    y0 = fmaxf(y0, 0.f); y1 = fmaxf(y1, 0.f);
                    if (layer > 0) {
                        float2 rv = __half22float2(
                            *(const __half2*)(xin_h + (size_t)n * HH + col));
                        y0 += rv.x; y1 += rv.y;
                    }
                    *(__half2*)(xout_h + (size_t)n * HH + col) = __floats2half2_rn(y0, y1);
                }
            }
        }
}

// ---------------- JK head: K=512 fp16 GEMM + bias ---------------------------
__global__ __launch_bounds__(256) void jk_k(
    const float* __restrict__ jkb, float* __restrict__ out) {
    extern __shared__ unsigned smem_u[];
    int tid = threadIdx.x, wid = tid >> 5, lane = tid & 31;
    int wm = wid & 3, wn = wid >> 2;
    int n0 = blockIdx.x * 128;
    uint32_t sh_base = (uint32_t)__cvta_generic_to_shared(smem_u);
    const __half* WH = g_jkWb[0];
    const __half* WL = g_jkWb[1];

    float acc[2][8][4];
    #pragma unroll
    for (int mt = 0; mt < 2; mt++)
        #pragma unroll
        for (int nt = 0; nt < 8; nt++)
            #pragma unroll
            for (int c = 0; c < 4; c++) acc[mt][nt][c] = 0.f;

    auto issue = [&](int ch) {
        uint32_t b = sh_base + (uint32_t)(ch & 1) * 3 * PLANE * 4;
        const __half* As = g_xb[ch >> 2] + (size_t)n0 * HH;
        cp_tile(b, tid, As, HH, (ch & 3) * 32);
        int k0 = ch * 32;
        cp_tile(b + PLANE * 4,     tid, WH, 512, k0);
        cp_tile(b + 2 * PLANE * 4, tid, WL, 512, k0);
    };

    issue(0);
    CP_COMMIT();
    #pragma unroll 1
    for (int ch = 0; ch < 16; ch++) {
        CP_WAIT(0);
        __syncthreads();
        if (ch + 1 < 16) { issue(ch + 1); CP_COMMIT(); }
        mma_chunk16(acc, sh_base, ch & 1, wm, wn, lane);
        __syncthreads();
    }

    int cbase = wn * 64 + (lane & 3) * 2;
    float bb[8][2];
    #pragma unroll
    for (int nt = 0; nt < 8; nt++) {
        int col = cbase + nt * 8;
        bb[nt][0] = jkb[col]; bb[nt][1] = jkb[col + 1];
    }
    #pragma unroll
    for (int mt = 0; mt < 2; mt++)
        #pragma unroll
        for (int rr = 0; rr < 2; rr++) {
            int rb = wm * 32 + mt * 16 + rr * 8 + (lane >> 2);
            int n = n0 + rb;
            if (n < NN) {
                #pragma unroll
                for (int nt = 0; nt < 8; nt++) {
                    int col = cbase + nt * 8;
                    *(float2*)(out + (size_t)n * HH + col) =
                        make_float2(acc[mt][nt][rr*2+0] + bb[nt][0],
                                    acc[mt][nt][rr*2+1] + bb[nt][1]);
                }
            }
        }
}

// ---------------- launch ----------------------------------------------------
extern "C" void kernel_launch(void* const* d_in, const int* in_sizes, int n_in,
                              void* d_out, int out_size) {
    const float* emb   = (const float*)d_in[0];
    const float* Wl    = (const float*)d_in[1];
    const float* bl    = (const float*)d_in[2];
    const float* Wr    = (const float*)d_in[3];
    const float* gamma = (const float*)d_in[4];
    const float* beta  = (const float*)d_in[5];
    const float* jkW   = (const float*)d_in[6];
    const float* jkb   = (const float*)d_in[7];
    const int*   eidx  = (const int*)d_in[8];
    const int* src = eidx;
    const int* dst = eidx + NE;
    float* out = (float*)d_out;

    const int SMEMSZ = 6 * PLANE * 4 + 4 * 512;   // 61440 + 2048 = 63488 B
    static bool attr_set = false;
    if (!attr_set) {
        cudaFuncSetAttribute(gemm_ln_k, cudaFuncAttributeMaxDynamicSharedMemorySize, SMEMSZ);
        cudaFuncSetAttribute(jk_k,      cudaFuncAttributeMaxDynamicSharedMemorySize, SMEMSZ);
        attr_set = true;
    }

    // init grid covers emb pairs (6.4M) > weight work
    const int initB = ((NN * HH / 2) + 255) / 256;
    init_k<<<initB, 256>>>(Wl, Wr, jkW, emb);        // 0
    count_k<<<(NE + 255) / 256, 256>>>(dst);          // 1
    scan1_k<<<NB, 1024>>>();                          // 2
    scan2_k<<<1, 128>>>();                            // 3
    fill_k<<<(NE + 255) / 256, 256>>>(src, dst);      // 4

    const int GB = (NN + 127) / 128;   // 782
    for (int l = 0; l < NL; l++) {
        agg_k<<<(NN + 15) / 16, 256>>>(l);            // 5 (profiled), 7, 9
        gemm_ln_k<<<GB, 256, SMEMSZ>>>(l, bl, gamma, beta);  // 6, 8, 10
    }
    jk_k<<<GB, 256, SMEMSZ>>>(jkb, out);              // 11
}

// round 13
// speedup vs baseline: 2.4359x; 1.2591x over previous
#include <cuda_runtime.h>
#include <cuda_fp16.h>
#include <stdint.h>

#define NN 100000
#define HH 128
#define NE 1600000
#define NB 98   // scan blocks = ceil(NN/1024)
#define NL 3

#define STRD 20              // smem row stride in 32-bit words (ldmatrix conflict-free)
#define PLANE (128 * STRD)   // one 128-row plane, in words
#define NPAD (NN + 128)      // padded rows so tail-block cp.async stays in bounds

// ---------------- scratch (device globals) ----------------------------------
__device__ int   g_cnt[NN];
__device__ int   g_cursor[NN];
__device__ int   g_rowptr[NN + 1];   // per-block partial exclusive scan (+ g_blksum[b])
__device__ int   g_csr[NE];
__device__ int   g_blksum[128];
__device__ float g_invdeg[NN];
__device__ __half g_aggh[(size_t)NPAD * HH];   // fp16 aggregation output (GEMM A)
__device__ __half g_xb[4][(size_t)NPAD * HH];  // fp16 activations: emb, x0, x1, x2
// weights fp16 (single plane), layout [h][k] (k contiguous)
__device__ __half g_Wh[NL][128 * 256];
__device__ __half g_jkWh[128 * 512];

// ---------------- helpers ----------------------------------------------------
#define MMA16816(d, a, b) asm volatile( \
    "mma.sync.aligned.m16n8k16.row.col.f32.f16.f16.f32 " \
    "{%0,%1,%2,%3}, {%4,%5,%6,%7}, {%8,%9}, {%0,%1,%2,%3};" \
    : "+f"((d)[0]), "+f"((d)[1]), "+f"((d)[2]), "+f"((d)[3]) \
    : "r"((a)[0]), "r"((a)[1]), "r"((a)[2]), "r"((a)[3]), \
      "r"((b)[0]), "r"((b)[1]))

__device__ __forceinline__ void ldsm4(unsigned* r, uint32_t addr) {
    asm volatile("ldmatrix.sync.aligned.m8n8.x4.shared.b16 {%0,%1,%2,%3}, [%4];"
                 : "=r"(r[0]), "=r"(r[1]), "=r"(r[2]), "=r"(r[3]) : "r"(addr));
}

#define CP16(dst, src) asm volatile("cp.async.cg.shared.global [%0], [%1], 16;" :: "r"(dst), "l"(src))
#define CP_COMMIT()    asm volatile("cp.async.commit_group;")
#define CP_WAIT(n)     asm volatile("cp.async.wait_group %0;" :: "n"(n))

// ---------------- setup: weights->fp16, emb->fp16, edge counting ------------
// g_cnt / g_cursor are zeroed by cudaMemsetAsync before this kernel.
__global__ void init_k(const float* __restrict__ Wl, const float* __restrict__ Wr,
                       const float* __restrict__ jkW, const float* __restrict__ emb,
                       const int* __restrict__ dst) {
    int i = blockIdx.x * blockDim.x + threadIdx.x;
    const int totW = NL * 128 * 256;
    if (i < totW) {
        int l = i >> 15;
        int rem = i & 32767;
        int h = rem >> 8, k = rem & 255;
        float w = (k < 128) ? Wl[l * 16384 + h * 128 + k]
                            : Wr[l * 16384 + h * 128 + (k - 128)];
        g_Wh[l][rem] = __float2half_rn(w);
    } else if (i < totW + 128 * 512) {
        int j = i - totW;
        g_jkWh[j] = __float2half_rn(jkW[j]);
    }
    if (i < NE) atomicAdd(&g_cnt[dst[i]], 1);
    size_t p = (size_t)i * 2;
    if (p < (size_t)NN * HH) {
        float2 v = *(const float2*)(emb + p);
        *(__half2*)(&g_xb[0][p]) = __floats2half2_rn(v.x, v.y);
    }
}

// scan phase 1: per-block exclusive scan + block totals (+ invdeg)
__global__ void scan1_k() {
    __shared__ int sh[1024];
    int i = blockIdx.x * 1024 + threadIdx.x;
    int v = (i < NN) ? g_cnt[i] : 0;
    sh[threadIdx.x] = v;
    __syncthreads();
    #pragma unroll
    for (int off = 1; off < 1024; off <<= 1) {
        int t = (threadIdx.x >= (unsigned)off) ? sh[threadIdx.x - off] : 0;
        __syncthreads();
        sh[threadIdx.x] += t;
        __syncthreads();
    }
    if (i < NN) {
        g_rowptr[i] = sh[threadIdx.x] - v;
        g_invdeg[i] = 1.0f / fmaxf((float)v, 1.0f);
    }
    if (threadIdx.x == 1023) g_blksum[blockIdx.x] = sh[1023];
}
// scan phase 2: exclusive-scan block totals in place (consumers add inline)
__global__ void scan2_k() {
    __shared__ int sh[128];
    int t = threadIdx.x;
    int v = (t < NB) ? g_blksum[t] : 0;
    sh[t] = v;
    __syncthreads();
    #pragma unroll
    for (int off = 1; off < 128; off <<= 1) {
        int u = (t >= off) ? sh[t - off] : 0;
        __syncthreads();
        sh[t] += u;
        __syncthreads();
    }
    if (t < NB) g_blksum[t] = sh[t] - v;
    if (t == 127) g_rowptr[NN] = NE;
}

__global__ void fill_k(const int* __restrict__ src, const int* __restrict__ dst) {
    int i = blockIdx.x * blockDim.x + threadIdx.x;
    if (i < NE) {
        int d = dst[i];
        int pos = g_rowptr[d] + g_blksum[d >> 10] + atomicAdd(&g_cursor[d], 1);
        g_csr[pos] = src[i];
    }
}

// ---------------- aggregation: 2 nodes/warp, 16 lanes each, uint4 loads -----
__global__ void agg_k(int layer) {
    const __half* __restrict__ x = g_xb[layer];
    int gid = blockIdx.x * blockDim.x + threadIdx.x;
    int warp = gid >> 5;
    int lane = threadIdx.x & 31;
    int sub = lane >> 4, ln = lane & 15;
    int node = warp * 2 + sub;
    if (node >= NN) return;
    int beg = g_rowptr[node] + g_blksum[node >> 10];
    int end = (node + 1 < NN) ? (g_rowptr[node + 1] + g_blksum[(node + 1) >> 10]) : NE;
    const __half* xb = x + ln * 8;
    float acc[8];
    #pragma unroll
    for (int t = 0; t < 8; t++) acc[t] = 0.f;
    int j = beg;
    for (; j + 3 < end; j += 4) {
        uint4 u[4];
        #pragma unroll
        for (int q = 0; q < 4; q++) {
            int s = g_csr[j + q];
            u[q] = *(const uint4*)(xb + (size_t)s * HH);
        }
        #pragma unroll
        for (int q = 0; q < 4; q++) {
            const __half2* h = (const __half2*)&u[q];
            #pragma unroll
            for (int t = 0; t < 4; t++) {
                float2 f = __half22float2(h[t]);
                acc[t * 2] += f.x; acc[t * 2 + 1] += f.y;
            }
        }
    }
    for (; j < end; j++) {
        int s = g_csr[j];
        uint4 uu = *(const uint4*)(xb + (size_t)s * HH);
        const __half2* h = (const __half2*)&uu;
        #pragma unroll
        for (int t = 0; t < 4; t++) {
            float2 f = __half22float2(h[t]);
            acc[t * 2] += f.x; acc[t * 2 + 1] += f.y;
        }
    }
    float inv = g_invdeg[node];
    __half2 o[4];
    #pragma unroll
    for (int t = 0; t < 4; t++)
        o[t] = __floats2half2_rn(acc[t * 2] * inv, acc[t * 2 + 1] * inv);
    *(uint4*)(g_aggh + (size_t)node * HH + ln * 8) = *(uint4*)o;
}

// ---------------- GEMM machinery --------------------------------------------
// buffer layout (words): buf b at b*2*PLANE: [A][B]; red floats after both bufs

__device__ __forceinline__ void cp_tile(uint32_t dstBase, int tid,
                                        const __half* srcBase, int rowStride, int off) {
    #pragma unroll
    for (int it = 0; it < 2; it++) {
        int c = tid + it * 256;
        int row = c >> 2, part = c & 3;
        uint32_t d = dstBase + (uint32_t)(row * STRD + part * 4) * 4;
        const __half* s = srcBase + (size_t)row * rowStride + off + part * 8;
        CP16(d, s);
    }
}

// single-term fp16 MMA over one 32-k chunk
__device__ __forceinline__ void mma_chunk16(
    float acc[2][8][4], uint32_t sh_base, int cur, int wm, int wn, int lane) {
    int lr = lane & 7, lg8 = ((lane >> 3) & 1) * 8, lk4 = ((lane >> 4) & 1) * 4;
    uint32_t base = sh_base + (uint32_t)cur * 2 * PLANE * 4;
    uint32_t rowA = (uint32_t)(wm * 32 + lg8 + lr) * (STRD * 4);
    uint32_t rowB0 = (uint32_t)(wn * 64 + lg8 + lr) * (STRD * 4);
    #pragma unroll
    for (int s = 0; s < 2; s++) {
        uint32_t kb = (uint32_t)(s * 8 + lk4) * 4;
        unsigned a0[4], a1[4], bh[8][2];
        ldsm4(a0, base + rowA + kb);
        ldsm4(a1, base + rowA + 16 * (STRD * 4) + kb);
        #pragma unroll
        for (int nt2 = 0; nt2 < 4; nt2++) {
            unsigned t[4];
            uint32_t rb = rowB0 + (uint32_t)(nt2 * 16) * (STRD * 4) + kb;
            ldsm4(t, base + PLANE * 4 + rb);
            bh[2*nt2][0] = t[0]; bh[2*nt2+1][0] = t[1];
            bh[2*nt2][1] = t[2]; bh[2*nt2+1][1] = t[3];
        }
        #pragma unroll
        for (int mt = 0; mt < 2; mt++) {
            const unsigned* a = mt ? a1 : a0;
            #pragma unroll
            for (int nt = 0; nt < 8; nt++)
                MMA16816(acc[mt][nt], a, bh[nt]);
        }
    }
}

// ---------------- fused GEMM (K=256) + bias + LN + ReLU + residual ---------
__global__ __launch_bounds__(256) void gemm_ln_k(
    int layer,
    const float* __restrict__ bl_all,
    const float* __restrict__ gamma_all, const float* __restrict__ beta_all) {
    extern __shared__ unsigned smem_u[];
    float* red = (float*)(smem_u + 4 * PLANE);   // red_s[2][128], red_q[2][128]

    const __half* __restrict__ xin_h = g_xb[layer];
    __half* __restrict__ xout_h = g_xb[layer + 1];
    const __half* WH = g_Wh[layer];
    const float* __restrict__ bias  = bl_all + layer * 128;
    const float* __restrict__ gamma = gamma_all + layer * 128;
    const float* __restrict__ beta  = beta_all + layer * 128;

    int tid = threadIdx.x, wid = tid >> 5, lane = tid & 31;
    int wm = wid & 3, wn = wid >> 2;
    int n0 = blockIdx.x * 128;
    uint32_t sh_base = (uint32_t)__cvta_generic_to_shared(smem_u);
    const __half* aggBase = g_aggh + (size_t)n0 * HH;
    const __half* xbBase  = xin_h + (size_t)n0 * HH;

    float acc[2][8][4];
    #pragma unroll
    for (int mt = 0; mt < 2; mt++)
        #pragma unroll
        for (int nt = 0; nt < 8; nt++)
            #pragma unroll
            for (int c = 0; c < 4; c++) acc[mt][nt][c] = 0.f;

    auto issue = [&](int ch) {
        uint32_t b = sh_base + (uint32_t)(ch & 1) * 2 * PLANE * 4;
        int k0 = ch * 32;
        if (k0 < HH) cp_tile(b, tid, aggBase, HH, k0);
        else         cp_tile(b, tid, xbBase,  HH, k0 - HH);
        cp_tile(b + PLANE * 4, tid, WH, 256, k0);
    };

    issue(0);
    CP_COMMIT();
    #pragma unroll 1
    for (int ch = 0; ch < 8; ch++) {
        CP_WAIT(0);
        __syncthreads();
        if (ch + 1 < 8) { issue(ch + 1); CP_COMMIT(); }
        mma_chunk16(acc, sh_base, ch & 1, wm, wn, lane);
        __syncthreads();
    }

    // ---- epilogue: bias -> LN -> ReLU -> residual(fp16) ----
    float* red_s = red;            // [2][128]
    float* red_q = red + 256;      // [2][128]
    int cbase = wn * 64 + (lane & 3) * 2;
    float bb[8][2], gg[8][2], be[8][2];
    #pragma unroll
    for (int nt = 0; nt < 8; nt++) {
        int col = cbase + nt * 8;
        bb[nt][0] = bias[col];  bb[nt][1] = bias[col + 1];
        gg[nt][0] = gamma[col]; gg[nt][1] = gamma[col + 1];
        be[nt][0] = beta[col];  be[nt][1] = beta[col + 1];
    }
    #pragma unroll
    for (int mt = 0; mt < 2; mt++)
        #pragma unroll
        for (int rr = 0; rr < 2; rr++) {
            float s = 0.f, q2 = 0.f;
            #pragma unroll
            for (int nt = 0; nt < 8; nt++)
                #pragma unroll
                for (int q = 0; q < 2; q++) {
                    float v = acc[mt][nt][rr * 2 + q] + bb[nt][q];
                    acc[mt][nt][rr * 2 + q] = v;
                    s += v; q2 += v * v;
                }
            s  += __shfl_xor_sync(0xffffffffu, s, 1);
            s  += __shfl_xor_sync(0xffffffffu, s, 2);
            q2 += __shfl_xor_sync(0xffffffffu, q2, 1);
            q2 += __shfl_xor_sync(0xffffffffu, q2, 2);
            if ((lane & 3) == 0) {
                int rb = wm * 32 + mt * 16 + rr * 8 + (lane >> 2);
                red_s[wn * 128 + rb] = s; red_q[wn * 128 + rb] = q2;
            }
        }
    __syncthreads();
    const float inv128 = 1.0f / 128.0f;
    #pragma unroll
    for (int mt = 0; mt < 2; mt++)
        #pragma unroll
        for (int rr = 0; rr < 2; rr++) {
            int rb = wm * 32 + mt * 16 + rr * 8 + (lane >> 2);
            int n = n0 + rb;
            float S = red_s[rb] + red_s[128 + rb];
            float Q = red_q[rb] + red_q[128 + rb];
            float mu = S * inv128;
            float var = Q * inv128 - mu * mu;
            float rs = rsqrtf(var + 1e-5f);
            if (n < NN) {
                #pragma unroll
                for (int nt = 0; nt < 8; nt++) {
                    int col = cbase + nt * 8;
                    float y0 = (acc[mt][nt][rr*2+0] - mu) * rs * gg[nt][0] + be[nt][0];
                    float y1 = (acc[mt][nt][rr*2+1] - mu) * rs * gg[nt][1] + be[nt][1];
                    y0 = fmaxf(y0, 0.f); y1 = fmaxf(y1, 0.f);
                    if (layer > 0) {
                        float2 rv = __half22float2(
                            *(const __half2*)(xin_h + (size_t)n * HH + col));
                        y0 += rv.x; y1 += rv.y;
                    }
                    *(__half2*)(xout_h + (size_t)n * HH + col) = __floats2half2_rn(y0, y1);
                }
            }
        }
}

// ---------------- JK head: K=512 fp16 GEMM + bias ---------------------------
__global__ __launch_bounds__(256) void jk_k(
    const float* __restrict__ jkb, float* __restrict__ out) {
    extern __shared__ unsigned smem_u[];
    int tid = threadIdx.x, wid = tid >> 5, lane = tid & 31;
    int wm = wid & 3, wn = wid >> 2;
    int n0 = blockIdx.x * 128;
    uint32_t sh_base = (uint32_t)__cvta_generic_to_shared(smem_u);
    const __half* WH = g_jkWh;

    float acc[2][8][4];
    #pragma unroll
    for (int mt = 0; mt < 2; mt++)
        #pragma unroll
        for (int nt = 0; nt < 8; nt++)
            #pragma unroll
            for (int c = 0; c < 4; c++) acc[mt][nt][c] = 0.f;

    auto issue = [&](int ch) {
        uint32_t b = sh_base + (uint32_t)(ch & 1) * 2 * PLANE * 4;
        const __half* As = g_xb[ch >> 2] + (size_t)n0 * HH;
        cp_tile(b, tid, As, HH, (ch & 3) * 32);
        cp_tile(b + PLANE * 4, tid, WH, 512, ch * 32);
    };

    issue(0);
    CP_COMMIT();
    #pragma unroll 1
    for (int ch = 0; ch < 16; ch++) {
        CP_WAIT(0);
        __syncthreads();
        if (ch + 1 < 16) { issue(ch + 1); CP_COMMIT(); }
        mma_chunk16(acc, sh_base, ch & 1, wm, wn, lane);
        __syncthreads();
    }

    int cbase = wn * 64 + (lane & 3) * 2;
    float bb[8][2];
    #pragma unroll
    for (int nt = 0; nt < 8; nt++) {
        int col = cbase + nt * 8;
        bb[nt][0] = jkb[col]; bb[nt][1] = jkb[col + 1];
    }
    #pragma unroll
    for (int mt = 0; mt < 2; mt++)
        #pragma unroll
        for (int rr = 0; rr < 2; rr++) {
            int rb = wm * 32 + mt * 16 + rr * 8 + (lane >> 2);
            int n = n0 + rb;
            if (n < NN) {
                #pragma unroll
                for (int nt = 0; nt < 8; nt++) {
                    int col = cbase + nt * 8;
                    *(float2*)(out + (size_t)n * HH + col) =
                        make_float2(acc[mt][nt][rr*2+0] + bb[nt][0],
                                    acc[mt][nt][rr*2+1] + bb[nt][1]);
                }
            }
        }
}

// ---------------- launch ----------------------------------------------------
extern "C" void kernel_launch(void* const* d_in, const int* in_sizes, int n_in,
                              void* d_out, int out_size) {
    const float* emb   = (const float*)d_in[0];
    const float* Wl    = (const float*)d_in[1];
    const float* bl    = (const float*)d_in[2];
    const float* Wr    = (const float*)d_in[3];
    const float* gamma = (const float*)d_in[4];
    const float* beta  = (const float*)d_in[5];
    const float* jkW   = (const float*)d_in[6];
    const float* jkb   = (const float*)d_in[7];
    const int*   eidx  = (const int*)d_in[8];
    const int* src = eidx;
    const int* dst = eidx + NE;
    float* out = (float*)d_out;

    const int SMEMSZ = 4 * PLANE * 4 + 4 * 512;   // 40960 + 2048 = 43008 B
    static bool attr_set = false;
    if (!attr_set) {
        cudaFuncSetAttribute(gemm_ln_k, cudaFuncAttributeMaxDynamicSharedMemorySize, SMEMSZ);
        cudaFuncSetAttribute(jk_k,      cudaFuncAttributeMaxDynamicSharedMemorySize, SMEMSZ);
        attr_set = true;
    }

    void* cntp = nullptr; void* curp = nullptr;
    cudaGetSymbolAddress(&cntp, g_cnt);
    cudaGetSymbolAddress(&curp, g_cursor);
    cudaMemsetAsync(cntp, 0, NN * sizeof(int));
    cudaMemsetAsync(curp, 0, NN * sizeof(int));

    const int initB = ((NN * HH / 2) + 255) / 256;
    init_k<<<initB, 256>>>(Wl, Wr, jkW, emb, dst);
    scan1_k<<<NB, 1024>>>();
    scan2_k<<<1, 128>>>();
    fill_k<<<(NE + 255) / 256, 256>>>(src, dst);

    const int GB = (NN + 127) / 128;   // 782
    for (int l = 0; l < NL; l++) {
        agg_k<<<(NN + 15) / 16, 256>>>(l);
        gemm_ln_k<<<GB, 256, SMEMSZ>>>(l, bl, gamma, beta);
    }
    jk_k<<<GB, 256, SMEMSZ>>>(jkb, out);
}